// round 14
// baseline (speedup 1.0000x reference)
#include <cuda_runtime.h>
#include <cuda_bf16.h>
#include <cstdint>
#include <math.h>

#define Dm   2048
#define Bb   4
#define Tt   2048
#define Hh   32
#define HSm  64
#define MROWS 8192
#define YSZ  (MROWS*Dm)
#define WSZ  (Dm*Dm)

typedef unsigned int u32;
typedef __nv_bfloat16 bf16;

// ---------------- static device scratch --------------------------------------
__device__ float g_k[YSZ], g_v[YSZ], g_u[YSZ], g_r[YSZ];
__device__ bf16  g_xnh[YSZ], g_xnl[YSZ], g_oh[YSZ], g_ol[YSZ];
__device__ bf16  g_Wh[6][WSZ], g_Wl[6][WSZ];     // 0=Wx^T 1=Ww 2=Wk 3=Wv 4=Wr 5=Wo
__device__ bf16  g_Wfh[WSZ], g_Wfl[WSZ];         // fused Ww@Wx

// ---------------- helpers ------------------------------------------------------
#define CPA(dst,src)   asm volatile("cp.async.cg.shared.global [%0], [%1], 16;" :: "r"(dst), "l"(src))
#define CPCOMMIT()     asm volatile("cp.async.commit_group;" ::: "memory")
#define CPWAIT(n)      asm volatile("cp.async.wait_group %0;" :: "n"(n) : "memory")

__device__ __forceinline__ u32 s2u(const void* p){
    u32 a; asm("{ .reg .u64 t; cvta.to.shared.u64 t, %1; cvt.u32.u64 %0, t; }" : "=r"(a) : "l"(p)); return a;
}

__device__ __forceinline__ void mma16816(float* c, const u32* a, const u32* b){
    asm volatile("mma.sync.aligned.m16n8k16.row.col.f32.bf16.bf16.f32 "
        "{%0,%1,%2,%3}, {%4,%5,%6,%7}, {%8,%9}, {%0,%1,%2,%3};"
        : "+f"(c[0]), "+f"(c[1]), "+f"(c[2]), "+f"(c[3])
        : "r"(a[0]), "r"(a[1]), "r"(a[2]), "r"(a[3]), "r"(b[0]), "r"(b[1]));
}

#define LDSM4(r0,r1,r2,r3,addr) \
    asm volatile("ldmatrix.sync.aligned.m8n8.x4.shared.b16 {%0,%1,%2,%3}, [%4];" \
        : "=r"(r0), "=r"(r1), "=r"(r2), "=r"(r3) : "r"(addr))

union BF2U { __nv_bfloat162 h; u32 u; };

__device__ __forceinline__ void split4(float4 v, uint2& H, uint2& L){
    BF2U h0, h1, l0, l1;
    h0.h = __floats2bfloat162_rn(v.x, v.y);
    h1.h = __floats2bfloat162_rn(v.z, v.w);
    float lx = v.x - __bfloat162float(h0.h.x);
    float ly = v.y - __bfloat162float(h0.h.y);
    float lz = v.z - __bfloat162float(h1.h.x);
    float lw = v.w - __bfloat162float(h1.h.y);
    l0.h = __floats2bfloat162_rn(lx, ly);
    l1.h = __floats2bfloat162_rn(lz, lw);
    H.x = h0.u; H.y = h1.u; L.x = l0.u; L.y = l1.u;
}

// ---------------- weight split (5 normal + 1 transpose in ONE launch) ---------
__global__ __launch_bounds__(256) void conv_all(
    const float* __restrict__ sWx,
    const float* __restrict__ s0, const float* __restrict__ s1,
    const float* __restrict__ s2, const float* __restrict__ s3,
    const float* __restrict__ s4,
    bf16* __restrict__ dh, bf16* __restrict__ dl)
{
    __shared__ float tile[32][33];
    const int wi = blockIdx.y;
    if (wi < 5) {
        const float* src = wi==0?s0 : wi==1?s1 : wi==2?s2 : wi==3?s3 : s4;
        int i = blockIdx.x * 256 + threadIdx.x;
        float4 v = ((const float4*)src)[i];
        uint2 H, L;
        split4(v, H, L);
        size_t o = (size_t)(wi+1) * (WSZ/4) + i;
        ((uint2*)dh)[o] = H; ((uint2*)dl)[o] = L;
    } else {
        const int bx = (blockIdx.x & 63) * 32;
        const int by = (blockIdx.x >> 6) * 32;
        const int tx = threadIdx.x & 31, ty = threadIdx.x >> 5;
        #pragma unroll
        for (int i = 0; i < 32; i += 8)
            tile[ty+i][tx] = sWx[(size_t)(by+ty+i)*Dm + bx+tx];
        __syncthreads();
        #pragma unroll
        for (int i = 0; i < 32; i += 8) {
            float v = tile[tx][ty+i];
            bf16 h = __float2bfloat16(v);
            bf16 l = __float2bfloat16(v - __bfloat162float(h));
            size_t o = (size_t)(bx+ty+i)*Dm + (by+tx);
            dh[o] = h; dl[o] = l;
        }
    }
}

// ---------------- LayerNorm -> hi/lo bf16 -------------------------------------
__global__ __launch_bounds__(256) void ln_kernel(
    const float* __restrict__ x, const float* __restrict__ gam,
    const float* __restrict__ bet, bf16* __restrict__ oh, bf16* __restrict__ ol)
{
    __shared__ float red[18];
    const int row = blockIdx.x;
    const int t = threadIdx.x;
    const float* xr = x + (size_t)row * Dm;

    float4 a0 = *(const float4*)(xr + 4*t);
    float4 a1 = *(const float4*)(xr + 1024 + 4*t);
    float s  = a0.x+a0.y+a0.z+a0.w + a1.x+a1.y+a1.z+a1.w;
    float ss = a0.x*a0.x+a0.y*a0.y+a0.z*a0.z+a0.w*a0.w
             + a1.x*a1.x+a1.y*a1.y+a1.z*a1.z+a1.w*a1.w;
    #pragma unroll
    for (int o = 16; o; o >>= 1) {
        s  += __shfl_xor_sync(0xffffffffu, s,  o);
        ss += __shfl_xor_sync(0xffffffffu, ss, o);
    }
    if ((t & 31) == 0) { red[t>>5] = s; red[8 + (t>>5)] = ss; }
    __syncthreads();
    if (t == 0) {
        float S = 0.f, SS = 0.f;
        #pragma unroll
        for (int i = 0; i < 8; i++) { S += red[i]; SS += red[8+i]; }
        float mu  = S * (1.0f/Dm);
        float var = SS * (1.0f/Dm) - mu*mu;
        red[16] = mu;
        red[17] = rsqrtf(var + 1e-5f);
    }
    __syncthreads();
    const float mu = red[16], rstd = red[17];

    float4 g0 = *(const float4*)(gam + 4*t);
    float4 g1 = *(const float4*)(gam + 1024 + 4*t);
    float4 b0 = *(const float4*)(bet + 4*t);
    float4 b1 = *(const float4*)(bet + 1024 + 4*t);
    float4 r0, r1;
    r0.x = (a0.x - mu)*rstd*g0.x + b0.x;
    r0.y = (a0.y - mu)*rstd*g0.y + b0.y;
    r0.z = (a0.z - mu)*rstd*g0.z + b0.z;
    r0.w = (a0.w - mu)*rstd*g0.w + b0.w;
    r1.x = (a1.x - mu)*rstd*g1.x + b1.x;
    r1.y = (a1.y - mu)*rstd*g1.y + b1.y;
    r1.z = (a1.z - mu)*rstd*g1.z + b1.z;
    r1.w = (a1.w - mu)*rstd*g1.w + b1.w;

    uint2 H, L;
    const size_t o0 = (size_t)row * Dm + 4*t;
    split4(r0, H, L);
    *(uint2*)(oh + o0) = H; *(uint2*)(ol + o0) = L;
    split4(r1, H, L);
    *(uint2*)(oh + o0 + 1024) = H; *(uint2*)(ol + o0 + 1024) = L;
}

// ---------------- split-bf16 mma.sync GEMM core -------------------------------
// CTA 128x128, BK=32, 8 warps (2x4), warp tile 64x32, double-buffered cp.async.
// smem rows padded to 80B. ldmatrix fragment loads, A streamed per m-tile.

#define OFF(tile,buf) ((buf)*40960u + (tile)*10240u)   // AH=0 AL=1 BH=2 BL=3
#define SMEM_BYTES 81920

#define EPI_NONE 0
#define EPI_SIG  1
#define EPI_USIG 2
#define EPI_HL   3

__device__ __forceinline__ void load_tiles(
    u32 sb, int buf, int t,
    const bf16* Ah, const bf16* Al, const bf16* Bh, const bf16* Bl,
    size_t arow, size_t brow, int k0)
{
    #pragma unroll
    for (int p = 0; p < 2; p++) {
        int i = t + p*256;
        int r = i >> 2, c16 = i & 3;
        u32 dst = (u32)(r*80 + c16*16);
        size_t go = (size_t)r*Dm + k0 + c16*8;
        CPA(sb + OFF(0,buf) + dst, (const char*)(Ah + arow + go));
        CPA(sb + OFF(1,buf) + dst, (const char*)(Al + arow + go));
        CPA(sb + OFF(2,buf) + dst, (const char*)(Bh + brow + go));
        CPA(sb + OFF(3,buf) + dst, (const char*)(Bl + brow + go));
    }
}

// ldmatrix-based chunk compute; aOff/bOff are lane row offsets (bytes)
__device__ __forceinline__ void gemm_chunk(
    u32 sb, int buf, u32 aOff, u32 bOff, float (&acc)[4][4][4])
{
    const u32 aH0 = sb + OFF(0,buf) + aOff;
    const u32 aL0 = sb + OFF(1,buf) + aOff;
    const u32 bH0 = sb + OFF(2,buf) + bOff;
    const u32 bL0 = sb + OFF(3,buf) + bOff;
    #pragma unroll
    for (int ks = 0; ks < 2; ks++) {
        const u32 ko = ks * 32;
        u32 bh[4][2], bl[4][2];
        #pragma unroll
        for (int ng = 0; ng < 2; ng++) {
            u32 h0,h1,h2,h3, L0,L1,L2,L3;
            LDSM4(h0,h1,h2,h3, bH0 + ng*1280u + ko);
            LDSM4(L0,L1,L2,L3, bL0 + ng*1280u + ko);
            bh[2*ng+0][0] = h0; bh[2*ng+0][1] = h2;
            bh[2*ng+1][0] = h1; bh[2*ng+1][1] = h3;
            bl[2*ng+0][0] = L0; bl[2*ng+0][1] = L2;
            bl[2*ng+1][0] = L1; bl[2*ng+1][1] = L3;
        }
        #pragma unroll
        for (int mt = 0; mt < 4; mt++) {
            u32 ah[4], al[4];
            LDSM4(ah[0], ah[1], ah[2], ah[3], aH0 + mt*1280u + ko);
            LDSM4(al[0], al[1], al[2], al[3], aL0 + mt*1280u + ko);
            #pragma unroll
            for (int nt = 0; nt < 4; nt++) {
                mma16816(acc[mt][nt], ah, bh[nt]);
                mma16816(acc[mt][nt], ah, bl[nt]);
                mma16816(acc[mt][nt], al, bh[nt]);
            }
        }
    }
}

__device__ __forceinline__ void epi_store_hl(
    bf16* Ch, bf16* Cl, int row0, int col, float v0, float v1, float v2, float v3)
{
    BF2U H0, H1, L0, L1;
    H0.h = __floats2bfloat162_rn(v0, v1);
    H1.h = __floats2bfloat162_rn(v2, v3);
    L0.h = __floats2bfloat162_rn(v0 - __bfloat162float(H0.h.x),
                                 v1 - __bfloat162float(H0.h.y));
    L1.h = __floats2bfloat162_rn(v2 - __bfloat162float(H1.h.x),
                                 v3 - __bfloat162float(H1.h.y));
    *(u32*)(Ch + (size_t)row0*Dm + col)     = H0.u;
    *(u32*)(Ch + (size_t)(row0+8)*Dm + col) = H1.u;
    *(u32*)(Cl + (size_t)row0*Dm + col)     = L0.u;
    *(u32*)(Cl + (size_t)(row0+8)*Dm + col) = L1.u;
}

// ---- batched GEMM over 4 weight sets (shared A), blockIdx.z selects set -----
struct GSet {
    const bf16* Bh; const bf16* Bl; const float* bias;
    float* C; bf16* Ch; bf16* Cl;
    int epi;
};

__global__ __launch_bounds__(256, 2) void gemm_batch(
    const bf16* __restrict__ Ah, const bf16* __restrict__ Al,
    GSet g0, GSet g1, GSet g2, GSet g3)
{
    extern __shared__ char sm[];
    const u32 sb = s2u(sm);
    const int t = threadIdx.x;
    const int w = t >> 5, lane = t & 31;
    const int wm = w >> 2, wn = w & 3;
    const int bn = blockIdx.x, bm = blockIdx.y, z = blockIdx.z;

    const bf16* Bh = (z==0) ? g0.Bh : (z==1) ? g1.Bh : (z==2) ? g2.Bh : g3.Bh;
    const bf16* Bl = (z==0) ? g0.Bl : (z==1) ? g1.Bl : (z==2) ? g2.Bl : g3.Bl;

    const size_t arow = (size_t)bm * 128 * Dm;
    const size_t brow = (size_t)bn * 128 * Dm;

    float acc[4][4][4];
    #pragma unroll
    for (int i = 0; i < 4; i++)
        #pragma unroll
        for (int j = 0; j < 4; j++)
            #pragma unroll
            for (int q = 0; q < 4; q++) acc[i][j][q] = 0.f;

    load_tiles(sb, 0, t, Ah, Al, Bh, Bl, arow, brow, 0);
    CPCOMMIT();

    const u32 l15 = lane & 15;
    const u32 lh16 = ((lane >> 4) & 1) * 16;
    const u32 aOff = (u32)(wm*64 + l15) * 80 + lh16;
    const u32 bOff = (u32)(wn*32 + l15) * 80 + lh16;

    for (int c = 0; c < 64; c++) {
        const int buf = c & 1;
        CPWAIT(0);
        __syncthreads();
        if (c + 1 < 64) {
            load_tiles(sb, buf ^ 1, t, Ah, Al, Bh, Bl, arow, brow, (c+1)*32);
            CPCOMMIT();
        }
        gemm_chunk(sb, buf, aOff, bOff, acc);
    }

    GSet gs = (z==0) ? g0 : (z==1) ? g1 : (z==2) ? g2 : g3;
    const int lq = lane >> 2;
    const int lr = lane & 3;
    #pragma unroll
    for (int mt = 0; mt < 4; mt++) {
        #pragma unroll
        for (int nt = 0; nt < 4; nt++) {
            int row0 = bm*128 + wm*64 + mt*16 + lq;
            int col  = bn*128 + wn*32 + nt*8 + lr*2;
            float v0 = acc[mt][nt][0], v1 = acc[mt][nt][1];
            float v2 = acc[mt][nt][2], v3 = acc[mt][nt][3];
            if (gs.epi == EPI_SIG) {
                v0 = 1.0f/(1.0f+__expf(-v0)); v1 = 1.0f/(1.0f+__expf(-v1));
                v2 = 1.0f/(1.0f+__expf(-v2)); v3 = 1.0f/(1.0f+__expf(-v3));
            }
            if (gs.epi == EPI_USIG) {
                float bb0 = __ldg(gs.bias + col), bb1 = __ldg(gs.bias + col + 1);
                v0 = 1.0f/(1.0f+__expf(v0+bb0)); v1 = 1.0f/(1.0f+__expf(v1+bb1));
                v2 = 1.0f/(1.0f+__expf(v2+bb0)); v3 = 1.0f/(1.0f+__expf(v3+bb1));
            }
            if (gs.epi == EPI_HL) {
                epi_store_hl(gs.Ch, gs.Cl, row0, col, v0, v1, v2, v3);
            } else {
                *(float2*)(gs.C + (size_t)row0*Dm + col)     = make_float2(v0, v1);
                *(float2*)(gs.C + (size_t)(row0+8)*Dm + col) = make_float2(v2, v3);
            }
        }
    }
}

// ---- single GEMM (templated epilogue): Wf weight-fuse (HL) and Wo (NONE) -----
template<int EPI>
__global__ __launch_bounds__(256, 2) void gemm_mma(
    const bf16* __restrict__ Ah, const bf16* __restrict__ Al,
    const bf16* __restrict__ Bh, const bf16* __restrict__ Bl,
    float* __restrict__ C, bf16* __restrict__ Ch, bf16* __restrict__ Cl)
{
    extern __shared__ char sm[];
    const u32 sb = s2u(sm);
    const int t = threadIdx.x;
    const int w = t >> 5, lane = t & 31;
    const int wm = w >> 2, wn = w & 3;
    const int bn = blockIdx.x, bm = blockIdx.y;

    const size_t arow = (size_t)bm * 128 * Dm;
    const size_t brow = (size_t)bn * 128 * Dm;

    float acc[4][4][4];
    #pragma unroll
    for (int i = 0; i < 4; i++)
        #pragma unroll
        for (int j = 0; j < 4; j++)
            #pragma unroll
            for (int q = 0; q < 4; q++) acc[i][j][q] = 0.f;

    load_tiles(sb, 0, t, Ah, Al, Bh, Bl, arow, brow, 0);
    CPCOMMIT();

    const u32 l15 = lane & 15;
    const u32 lh16 = ((lane >> 4) & 1) * 16;
    const u32 aOff = (u32)(wm*64 + l15) * 80 + lh16;
    const u32 bOff = (u32)(wn*32 + l15) * 80 + lh16;

    for (int c = 0; c < 64; c++) {
        const int buf = c & 1;
        CPWAIT(0);
        __syncthreads();
        if (c + 1 < 64) {
            load_tiles(sb, buf ^ 1, t, Ah, Al, Bh, Bl, arow, brow, (c+1)*32);
            CPCOMMIT();
        }
        gemm_chunk(sb, buf, aOff, bOff, acc);
    }

    const int lq = lane >> 2;
    const int lr = lane & 3;
    #pragma unroll
    for (int mt = 0; mt < 4; mt++) {
        #pragma unroll
        for (int nt = 0; nt < 4; nt++) {
            int row0 = bm*128 + wm*64 + mt*16 + lq;
            int col  = bn*128 + wn*32 + nt*8 + lr*2;
            float v0 = acc[mt][nt][0], v1 = acc[mt][nt][1];
            float v2 = acc[mt][nt][2], v3 = acc[mt][nt][3];
            if (EPI == EPI_HL) {
                epi_store_hl(Ch, Cl, row0, col, v0, v1, v2, v3);
            } else {
                *(float2*)(C + (size_t)row0*Dm + col)     = make_float2(v0, v1);
                *(float2*)(C + (size_t)(row0+8)*Dm + col) = make_float2(v2, v3);
            }
        }
    }
}

// ---------------- selective-WKV recurrent scan (cp.async double-buffered) -----
#define CH 8
__global__ __launch_bounds__(256) void scan_kernel(
    const float* __restrict__ kA, const float* __restrict__ vA,
    const float* __restrict__ uA, const float* __restrict__ rA,
    const float* __restrict__ state0, bf16* __restrict__ oh, bf16* __restrict__ ol,
    float* __restrict__ stateF)
{
    const int bh = blockIdx.x;
    const int b  = bh >> 5;
    const int h  = bh & 31;
    const size_t base = (size_t)b * Tt * Dm + (size_t)h * HSm;

    const int t  = threadIdx.x;
    const int ti = t >> 4;
    const int tj = t & 15;

    __shared__ float stg[2][4][CH][64];
    __shared__ float pS[CH][16][64];

    float S[4][4];
    const float* st0 = state0 + (size_t)bh * 4096;
    #pragma unroll
    for (int ii = 0; ii < 4; ii++) {
        float4 s4 = *(const float4*)(st0 + (ti*4+ii)*64 + tj*4);
        S[ii][0]=s4.x; S[ii][1]=s4.y; S[ii][2]=s4.z; S[ii][3]=s4.w;
    }

    const float* bases[4] = { kA + base, vA + base, uA + base, rA + base };

    const int i0 = t, i1 = t + 256;
    const int a0 = i0 >> 7, s0 = (i0 >> 4) & 7, q0 = i0 & 15;
    const int a1 = i1 >> 7, s1 = (i1 >> 4) & 7, q1 = i1 & 15;

    {
        u32 d0 = s2u(&stg[0][a0][s0][q0*4]);
        u32 d1 = s2u(&stg[0][a1][s1][q1*4]);
        CPA(d0, (const char*)(bases[a0] + (size_t)s0*Dm + q0*4));
        CPA(d1, (const char*)(bases[a1] + (size_t)s1*Dm + q1*4));
        CPCOMMIT();
    }

    for (int c = 0; c < Tt/CH; c++) {
        const int buf = c & 1;
        CPWAIT(0);
        __syncthreads();
        if (c + 1 < Tt/CH) {
            const size_t nco = (size_t)(c+1) * CH * Dm;
            u32 d0 = s2u(&stg[buf^1][a0][s0][q0*4]);
            u32 d1 = s2u(&stg[buf^1][a1][s1][q1*4]);
            CPA(d0, (const char*)(bases[a0] + nco + (size_t)s0*Dm + q0*4));
            CPA(d1, (const char*)(bases[a1] + nco + (size_t)s1*Dm + q1*4));
            CPCOMMIT();
        }

        #pragma unroll
        for (int s = 0; s < CH; s++) {
            float4 k4 = *(const float4*)(&stg[buf][0][s][ti*4]);
            float4 v4 = *(const float4*)(&stg[buf][1][s][tj*4]);
            float4 u4 = *(const float4*)(&stg[buf][2][s][ti*4]);
            float4 r4 = *(const float4*)(&stg[buf][3][s][ti*4]);
            float kv[4] = {k4.x,k4.y,k4.z,k4.w};
            float uv[4] = {u4.x,u4.y,u4.z,u4.w};
            float rv[4] = {r4.x,r4.y,r4.z,r4.w};
            float vv[4] = {v4.x,v4.y,v4.z,v4.w};
            float p0=0.f,p1=0.f,p2=0.f,p3=0.f;
            #pragma unroll
            for (int ii = 0; ii < 4; ii++) {
                S[ii][0] = fmaf(uv[ii], S[ii][0], kv[ii]*vv[0]);
                S[ii][1] = fmaf(uv[ii], S[ii][1], kv[ii]*vv[1]);
                S[ii][2] = fmaf(uv[ii], S[ii][2], kv[ii]*vv[2]);
                S[ii][3] = fmaf(uv[ii], S[ii][3], kv[ii]*vv[3]);
                p0 = fmaf(rv[ii], S[ii][0], p0);
                p1 = fmaf(rv[ii], S[ii][1], p1);
                p2 = fmaf(rv[ii], S[ii][2], p2);
                p3 = fmaf(rv[ii], S[ii][3], p3);
            }
            *(float4*)(&pS[s][ti][tj*4]) = make_float4(p0,p1,p2,p3);
        }
        __syncthreads();

        const size_t coff = (size_t)c * CH * Dm;
        #pragma unroll
        for (int q = 0; q < 2; q++) {
            int o = t + q*256;
            int s = o >> 6;
            int j = o & 63;
            float sum = 0.f;
            #pragma unroll
            for (int ii = 0; ii < 16; ii++) sum += pS[s][ii][j];
            size_t idx = base + coff + (size_t)s*Dm + j;
            bf16 hv = __float2bfloat16(sum);
            oh[idx] = hv;
            ol[idx] = __float2bfloat16(sum - __bfloat162float(hv));
        }
        __syncthreads();
    }

    float* sf = stateF + (size_t)bh * 4096;
    #pragma unroll
    for (int ii = 0; ii < 4; ii++)
        *(float4*)(sf + (ti*4+ii)*64 + tj*4)
            = make_float4(S[ii][0],S[ii][1],S[ii][2],S[ii][3]);
}

// ---------------- launch ------------------------------------------------------
extern "C" void kernel_launch(void* const* d_in, const int* in_sizes, int n_in,
                              void* d_out, int out_size)
{
    const float* x     = (const float*)d_in[0];
    const float* state = (const float*)d_in[1];
    const float* ln_g  = (const float*)d_in[2];
    const float* ln_b  = (const float*)d_in[3];
    const float* Wx    = (const float*)d_in[4];
    const float* Ww    = (const float*)d_in[5];
    const float* bw    = (const float*)d_in[6];
    const float* Wk    = (const float*)d_in[7];
    const float* Wv    = (const float*)d_in[8];
    const float* Wr    = (const float*)d_in[9];
    const float* Wo    = (const float*)d_in[10];

    float* y_out  = (float*)d_out;
    float* sf_out = (float*)d_out + YSZ;

    float *kk, *vv, *uu, *rr;
    bf16 *xnh, *xnl, *oh, *ol, *wfh, *wfl;
    bf16 *whbase, *wlbase;
    cudaGetSymbolAddress((void**)&kk,  g_k);
    cudaGetSymbolAddress((void**)&vv,  g_v);
    cudaGetSymbolAddress((void**)&uu,  g_u);
    cudaGetSymbolAddress((void**)&rr,  g_r);
    cudaGetSymbolAddress((void**)&xnh, g_xnh);
    cudaGetSymbolAddress((void**)&xnl, g_xnl);
    cudaGetSymbolAddress((void**)&oh,  g_oh);
    cudaGetSymbolAddress((void**)&ol,  g_ol);
    cudaGetSymbolAddress((void**)&wfh, g_Wfh);
    cudaGetSymbolAddress((void**)&wfl, g_Wfl);
    cudaGetSymbolAddress((void**)&whbase, g_Wh);
    cudaGetSymbolAddress((void**)&wlbase, g_Wl);
    bf16 *wh[6], *wl[6];
    for (int i = 0; i < 6; i++) { wh[i] = whbase + (size_t)i*WSZ; wl[i] = wlbase + (size_t)i*WSZ; }

    cudaFuncSetAttribute(gemm_batch,         cudaFuncAttributeMaxDynamicSharedMemorySize, SMEM_BYTES);
    cudaFuncSetAttribute(gemm_mma<EPI_HL>,   cudaFuncAttributeMaxDynamicSharedMemorySize, SMEM_BYTES);
    cudaFuncSetAttribute(gemm_mma<EPI_NONE>, cudaFuncAttributeMaxDynamicSharedMemorySize, SMEM_BYTES);

    // launch 0: weight splits (Ww,Wk,Wv,Wr,Wo normal; Wx transposed)
    {
        dim3 cg(4096, 6);
        conv_all<<<cg, 256>>>(Wx, Ww, Wk, Wv, Wr, Wo, whbase, wlbase);
    }

    // launch 1: LayerNorm -> split xn
    ln_kernel<<<MROWS, 256>>>(x, ln_g, ln_b, xnh, xnl);

    // launch 2: Wf = Ww @ Wx (split output)
    {
        dim3 gw(Dm/128, Dm/128);
        gemm_mma<EPI_HL><<<gw, 256, SMEM_BYTES>>>(wh[1], wl[1], wh[0], wl[0],
                                                  nullptr, wfh, wfl);
    }

    // launch 3: batched GEMMs over xn: Wf (USIG->u), Wk, Wv, Wr (SIG)
    {
        GSet s0 = { wfh, wfl, bw, uu, nullptr, nullptr, EPI_USIG };
        GSet s1 = { wh[2], wl[2], nullptr, kk, nullptr, nullptr, EPI_NONE };
        GSet s2 = { wh[3], wl[3], nullptr, vv, nullptr, nullptr, EPI_NONE };
        GSet s3 = { wh[4], wl[4], nullptr, rr, nullptr, nullptr, EPI_SIG };
        dim3 gg(Dm/128, MROWS/128, 4);
        gemm_batch<<<gg, 256, SMEM_BYTES>>>(xnh, xnl, s0, s1, s2, s3);
    }

    // launch 4: scan
    scan_kernel<<<Bb*Hh, 256>>>(kk, vv, uu, rr, state, oh, ol, sf_out);

    // launch 5: y = outs @ Wo^T
    {
        dim3 g1(Dm/128, MROWS/128);
        gemm_mma<EPI_NONE><<<g1, 256, SMEM_BYTES>>>(oh, ol, wh[5], wl[5],
                                                    y_out, nullptr, nullptr);
    }
}

// round 15
// speedup vs baseline: 1.0115x; 1.0115x over previous
#include <cuda_runtime.h>
#include <cuda_bf16.h>
#include <cstdint>
#include <math.h>

#define Dm   2048
#define Bb   4
#define Tt   2048
#define Hh   32
#define HSm  64
#define MROWS 8192
#define YSZ  (MROWS*Dm)
#define WSZ  (Dm*Dm)

typedef unsigned int u32;
typedef __nv_bfloat16 bf16;

// ---------------- static device scratch --------------------------------------
__device__ float g_k[YSZ], g_v[YSZ], g_u[YSZ], g_r[YSZ];
__device__ bf16  g_xnh[YSZ], g_xnl[YSZ], g_oh[YSZ], g_ol[YSZ];
__device__ bf16  g_Wh[6][WSZ], g_Wl[6][WSZ];     // 0=Wx^T 1=Ww 2=Wk 3=Wv 4=Wr 5=Wo
__device__ bf16  g_Wfh[WSZ], g_Wfl[WSZ];         // fused Ww@Wx

// ---------------- helpers ------------------------------------------------------
#define CPA(dst,src)   asm volatile("cp.async.cg.shared.global [%0], [%1], 16;" :: "r"(dst), "l"(src))
#define CPCOMMIT()     asm volatile("cp.async.commit_group;" ::: "memory")
#define CPWAIT(n)      asm volatile("cp.async.wait_group %0;" :: "n"(n) : "memory")

__device__ __forceinline__ u32 s2u(const void* p){
    u32 a; asm("{ .reg .u64 t; cvta.to.shared.u64 t, %1; cvt.u32.u64 %0, t; }" : "=r"(a) : "l"(p)); return a;
}

__device__ __forceinline__ void mma16816(float* c, const u32* a, const u32* b){
    asm volatile("mma.sync.aligned.m16n8k16.row.col.f32.bf16.bf16.f32 "
        "{%0,%1,%2,%3}, {%4,%5,%6,%7}, {%8,%9}, {%0,%1,%2,%3};"
        : "+f"(c[0]), "+f"(c[1]), "+f"(c[2]), "+f"(c[3])
        : "r"(a[0]), "r"(a[1]), "r"(a[2]), "r"(a[3]), "r"(b[0]), "r"(b[1]));
}

union BF2U { __nv_bfloat162 h; u32 u; };

__device__ __forceinline__ void split4(float4 v, uint2& H, uint2& L){
    BF2U h0, h1, l0, l1;
    h0.h = __floats2bfloat162_rn(v.x, v.y);
    h1.h = __floats2bfloat162_rn(v.z, v.w);
    float lx = v.x - __bfloat162float(h0.h.x);
    float ly = v.y - __bfloat162float(h0.h.y);
    float lz = v.z - __bfloat162float(h1.h.x);
    float lw = v.w - __bfloat162float(h1.h.y);
    l0.h = __floats2bfloat162_rn(lx, ly);
    l1.h = __floats2bfloat162_rn(lz, lw);
    H.x = h0.u; H.y = h1.u; L.x = l0.u; L.y = l1.u;
}

// ---------------- weight split (5 normal + 1 transpose in ONE launch) ---------
__global__ __launch_bounds__(256) void conv_all(
    const float* __restrict__ sWx,
    const float* __restrict__ s0, const float* __restrict__ s1,
    const float* __restrict__ s2, const float* __restrict__ s3,
    const float* __restrict__ s4,
    bf16* __restrict__ dh, bf16* __restrict__ dl)
{
    __shared__ float tile[32][33];
    const int wi = blockIdx.y;
    if (wi < 5) {
        const float* src = wi==0?s0 : wi==1?s1 : wi==2?s2 : wi==3?s3 : s4;
        int i = blockIdx.x * 256 + threadIdx.x;
        float4 v = ((const float4*)src)[i];
        uint2 H, L;
        split4(v, H, L);
        size_t o = (size_t)(wi+1) * (WSZ/4) + i;
        ((uint2*)dh)[o] = H; ((uint2*)dl)[o] = L;
    } else {
        const int bx = (blockIdx.x & 63) * 32;
        const int by = (blockIdx.x >> 6) * 32;
        const int tx = threadIdx.x & 31, ty = threadIdx.x >> 5;
        #pragma unroll
        for (int i = 0; i < 32; i += 8)
            tile[ty+i][tx] = sWx[(size_t)(by+ty+i)*Dm + bx+tx];
        __syncthreads();
        #pragma unroll
        for (int i = 0; i < 32; i += 8) {
            float v = tile[tx][ty+i];
            bf16 h = __float2bfloat16(v);
            bf16 l = __float2bfloat16(v - __bfloat162float(h));
            size_t o = (size_t)(bx+ty+i)*Dm + (by+tx);
            dh[o] = h; dl[o] = l;
        }
    }
}

// ---------------- LayerNorm -> hi/lo bf16 -------------------------------------
__global__ __launch_bounds__(256) void ln_kernel(
    const float* __restrict__ x, const float* __restrict__ gam,
    const float* __restrict__ bet, bf16* __restrict__ oh, bf16* __restrict__ ol)
{
    __shared__ float red[18];
    const int row = blockIdx.x;
    const int t = threadIdx.x;
    const float* xr = x + (size_t)row * Dm;

    float4 a0 = *(const float4*)(xr + 4*t);
    float4 a1 = *(const float4*)(xr + 1024 + 4*t);
    float s  = a0.x+a0.y+a0.z+a0.w + a1.x+a1.y+a1.z+a1.w;
    float ss = a0.x*a0.x+a0.y*a0.y+a0.z*a0.z+a0.w*a0.w
             + a1.x*a1.x+a1.y*a1.y+a1.z*a1.z+a1.w*a1.w;
    #pragma unroll
    for (int o = 16; o; o >>= 1) {
        s  += __shfl_xor_sync(0xffffffffu, s,  o);
        ss += __shfl_xor_sync(0xffffffffu, ss, o);
    }
    if ((t & 31) == 0) { red[t>>5] = s; red[8 + (t>>5)] = ss; }
    __syncthreads();
    if (t == 0) {
        float S = 0.f, SS = 0.f;
        #pragma unroll
        for (int i = 0; i < 8; i++) { S += red[i]; SS += red[8+i]; }
        float mu  = S * (1.0f/Dm);
        float var = SS * (1.0f/Dm) - mu*mu;
        red[16] = mu;
        red[17] = rsqrtf(var + 1e-5f);
    }
    __syncthreads();
    const float mu = red[16], rstd = red[17];

    float4 g0 = *(const float4*)(gam + 4*t);
    float4 g1 = *(const float4*)(gam + 1024 + 4*t);
    float4 b0 = *(const float4*)(bet + 4*t);
    float4 b1 = *(const float4*)(bet + 1024 + 4*t);
    float4 r0, r1;
    r0.x = (a0.x - mu)*rstd*g0.x + b0.x;
    r0.y = (a0.y - mu)*rstd*g0.y + b0.y;
    r0.z = (a0.z - mu)*rstd*g0.z + b0.z;
    r0.w = (a0.w - mu)*rstd*g0.w + b0.w;
    r1.x = (a1.x - mu)*rstd*g1.x + b1.x;
    r1.y = (a1.y - mu)*rstd*g1.y + b1.y;
    r1.z = (a1.z - mu)*rstd*g1.z + b1.z;
    r1.w = (a1.w - mu)*rstd*g1.w + b1.w;

    uint2 H, L;
    const size_t o0 = (size_t)row * Dm + 4*t;
    split4(r0, H, L);
    *(uint2*)(oh + o0) = H; *(uint2*)(ol + o0) = L;
    split4(r1, H, L);
    *(uint2*)(oh + o0 + 1024) = H; *(uint2*)(ol + o0 + 1024) = L;
}

// ---------------- split-bf16 mma.sync GEMM core (R13 proven config) -----------
// CTA 128x128, BK=32, 8 warps (2x4), warp tile 64x32, double-buffered cp.async.
// smem rows padded to 80B (40 bf16). Scalar LDS fragment loads.

#define OFF(tile,buf) ((buf)*40960u + (tile)*10240u)   // AH=0 AL=1 BH=2 BL=3
#define SMEM_BYTES 81920

#define EPI_NONE 0
#define EPI_SIG  1
#define EPI_USIG 2
#define EPI_HL   3

__device__ __forceinline__ void load_tiles(
    u32 sb, int buf, int t,
    const bf16* Ah, const bf16* Al, const bf16* Bh, const bf16* Bl,
    size_t arow, size_t brow, int k0)
{
    #pragma unroll
    for (int p = 0; p < 2; p++) {
        int i = t + p*256;
        int r = i >> 2, c16 = i & 3;
        u32 dst = (u32)(r*80 + c16*16);
        size_t go = (size_t)r*Dm + k0 + c16*8;
        CPA(sb + OFF(0,buf) + dst, (const char*)(Ah + arow + go));
        CPA(sb + OFF(1,buf) + dst, (const char*)(Al + arow + go));
        CPA(sb + OFF(2,buf) + dst, (const char*)(Bh + brow + go));
        CPA(sb + OFF(3,buf) + dst, (const char*)(Bl + brow + go));
    }
}

__device__ __forceinline__ void gemm_chunk(
    const bf16* sAh, const bf16* sAl, const bf16* sBh, const bf16* sBl,
    int wm, int wn, int lq, int lr, float (&acc)[4][4][4])
{
    #pragma unroll
    for (int ks = 0; ks < 2; ks++) {
        const int kofs = ks*16 + lr*2;
        u32 bh[4][2], bl[4][2];
        #pragma unroll
        for (int nt = 0; nt < 4; nt++) {
            int n0 = wn*32 + nt*8 + lq;
            bh[nt][0] = *(const u32*)(sBh + n0*40 + kofs);
            bh[nt][1] = *(const u32*)(sBh + n0*40 + kofs + 8);
            bl[nt][0] = *(const u32*)(sBl + n0*40 + kofs);
            bl[nt][1] = *(const u32*)(sBl + n0*40 + kofs + 8);
        }
        #pragma unroll
        for (int mt = 0; mt < 4; mt++) {
            int r0 = wm*64 + mt*16 + lq;
            u32 ah[4], al[4];
            ah[0] = *(const u32*)(sAh + r0*40 + kofs);
            ah[1] = *(const u32*)(sAh + (r0+8)*40 + kofs);
            ah[2] = *(const u32*)(sAh + r0*40 + kofs + 8);
            ah[3] = *(const u32*)(sAh + (r0+8)*40 + kofs + 8);
            al[0] = *(const u32*)(sAl + r0*40 + kofs);
            al[1] = *(const u32*)(sAl + (r0+8)*40 + kofs);
            al[2] = *(const u32*)(sAl + r0*40 + kofs + 8);
            al[3] = *(const u32*)(sAl + (r0+8)*40 + kofs + 8);
            #pragma unroll
            for (int nt = 0; nt < 4; nt++) {
                mma16816(acc[mt][nt], ah, bh[nt]);
                mma16816(acc[mt][nt], ah, bl[nt]);
                mma16816(acc[mt][nt], al, bh[nt]);
            }
        }
    }
}

__device__ __forceinline__ void epi_store_hl(
    bf16* Ch, bf16* Cl, int row0, int col, float v0, float v1, float v2, float v3)
{
    BF2U H0, H1, L0, L1;
    H0.h = __floats2bfloat162_rn(v0, v1);
    H1.h = __floats2bfloat162_rn(v2, v3);
    L0.h = __floats2bfloat162_rn(v0 - __bfloat162float(H0.h.x),
                                 v1 - __bfloat162float(H0.h.y));
    L1.h = __floats2bfloat162_rn(v2 - __bfloat162float(H1.h.x),
                                 v3 - __bfloat162float(H1.h.y));
    *(u32*)(Ch + (size_t)row0*Dm + col)     = H0.u;
    *(u32*)(Ch + (size_t)(row0+8)*Dm + col) = H1.u;
    *(u32*)(Cl + (size_t)row0*Dm + col)     = L0.u;
    *(u32*)(Cl + (size_t)(row0+8)*Dm + col) = L1.u;
}

// ---- batched GEMM over 4 weight sets (shared A), blockIdx.z selects set -----
struct GSet {
    const bf16* Bh; const bf16* Bl; const float* bias;
    float* C; bf16* Ch; bf16* Cl;
    int epi;
};

__global__ __launch_bounds__(256, 2) void gemm_batch(
    const bf16* __restrict__ Ah, const bf16* __restrict__ Al,
    GSet g0, GSet g1, GSet g2, GSet g3)
{
    extern __shared__ char sm[];
    const u32 sb = s2u(sm);
    const int t = threadIdx.x;
    const int w = t >> 5, lane = t & 31;
    const int wm = w >> 2, wn = w & 3;
    const int bn = blockIdx.x, bm = blockIdx.y, z = blockIdx.z;

    const bf16* Bh = (z==0) ? g0.Bh : (z==1) ? g1.Bh : (z==2) ? g2.Bh : g3.Bh;
    const bf16* Bl = (z==0) ? g0.Bl : (z==1) ? g1.Bl : (z==2) ? g2.Bl : g3.Bl;

    const size_t arow = (size_t)bm * 128 * Dm;
    const size_t brow = (size_t)bn * 128 * Dm;

    float acc[4][4][4];
    #pragma unroll
    for (int i = 0; i < 4; i++)
        #pragma unroll
        for (int j = 0; j < 4; j++)
            #pragma unroll
            for (int q = 0; q < 4; q++) acc[i][j][q] = 0.f;

    load_tiles(sb, 0, t, Ah, Al, Bh, Bl, arow, brow, 0);
    CPCOMMIT();

    const int lq = lane >> 2;
    const int lr = lane & 3;

    for (int c = 0; c < 64; c++) {
        const int buf = c & 1;
        CPWAIT(0);
        __syncthreads();
        if (c + 1 < 64) {
            load_tiles(sb, buf ^ 1, t, Ah, Al, Bh, Bl, arow, brow, (c+1)*32);
            CPCOMMIT();
        }
        gemm_chunk((const bf16*)(sm + OFF(0,buf)), (const bf16*)(sm + OFF(1,buf)),
                   (const bf16*)(sm + OFF(2,buf)), (const bf16*)(sm + OFF(3,buf)),
                   wm, wn, lq, lr, acc);
    }

    GSet gs = (z==0) ? g0 : (z==1) ? g1 : (z==2) ? g2 : g3;
    #pragma unroll
    for (int mt = 0; mt < 4; mt++) {
        #pragma unroll
        for (int nt = 0; nt < 4; nt++) {
            int row0 = bm*128 + wm*64 + mt*16 + lq;
            int col  = bn*128 + wn*32 + nt*8 + lr*2;
            float v0 = acc[mt][nt][0], v1 = acc[mt][nt][1];
            float v2 = acc[mt][nt][2], v3 = acc[mt][nt][3];
            if (gs.epi == EPI_SIG) {
                v0 = 1.0f/(1.0f+__expf(-v0)); v1 = 1.0f/(1.0f+__expf(-v1));
                v2 = 1.0f/(1.0f+__expf(-v2)); v3 = 1.0f/(1.0f+__expf(-v3));
            }
            if (gs.epi == EPI_USIG) {
                float bb0 = __ldg(gs.bias + col), bb1 = __ldg(gs.bias + col + 1);
                v0 = 1.0f/(1.0f+__expf(v0+bb0)); v1 = 1.0f/(1.0f+__expf(v1+bb1));
                v2 = 1.0f/(1.0f+__expf(v2+bb0)); v3 = 1.0f/(1.0f+__expf(v3+bb1));
            }
            if (gs.epi == EPI_HL) {
                epi_store_hl(gs.Ch, gs.Cl, row0, col, v0, v1, v2, v3);
            } else {
                *(float2*)(gs.C + (size_t)row0*Dm + col)     = make_float2(v0, v1);
                *(float2*)(gs.C + (size_t)(row0+8)*Dm + col) = make_float2(v2, v3);
            }
        }
    }
}

// ---- single GEMM (templated epilogue): Wf weight-fuse (HL) and Wo (NONE) -----
template<int EPI>
__global__ __launch_bounds__(256, 2) void gemm_mma(
    const bf16* __restrict__ Ah, const bf16* __restrict__ Al,
    const bf16* __restrict__ Bh, const bf16* __restrict__ Bl,
    float* __restrict__ C, bf16* __restrict__ Ch, bf16* __restrict__ Cl)
{
    extern __shared__ char sm[];
    const u32 sb = s2u(sm);
    const int t = threadIdx.x;
    const int w = t >> 5, lane = t & 31;
    const int wm = w >> 2, wn = w & 3;
    const int bn = blockIdx.x, bm = blockIdx.y;

    const size_t arow = (size_t)bm * 128 * Dm;
    const size_t brow = (size_t)bn * 128 * Dm;

    float acc[4][4][4];
    #pragma unroll
    for (int i = 0; i < 4; i++)
        #pragma unroll
        for (int j = 0; j < 4; j++)
            #pragma unroll
            for (int q = 0; q < 4; q++) acc[i][j][q] = 0.f;

    load_tiles(sb, 0, t, Ah, Al, Bh, Bl, arow, brow, 0);
    CPCOMMIT();

    const int lq = lane >> 2;
    const int lr = lane & 3;

    for (int c = 0; c < 64; c++) {
        const int buf = c & 1;
        CPWAIT(0);
        __syncthreads();
        if (c + 1 < 64) {
            load_tiles(sb, buf ^ 1, t, Ah, Al, Bh, Bl, arow, brow, (c+1)*32);
            CPCOMMIT();
        }
        gemm_chunk((const bf16*)(sm + OFF(0,buf)), (const bf16*)(sm + OFF(1,buf)),
                   (const bf16*)(sm + OFF(2,buf)), (const bf16*)(sm + OFF(3,buf)),
                   wm, wn, lq, lr, acc);
    }

    #pragma unroll
    for (int mt = 0; mt < 4; mt++) {
        #pragma unroll
        for (int nt = 0; nt < 4; nt++) {
            int row0 = bm*128 + wm*64 + mt*16 + lq;
            int col  = bn*128 + wn*32 + nt*8 + lr*2;
            float v0 = acc[mt][nt][0], v1 = acc[mt][nt][1];
            float v2 = acc[mt][nt][2], v3 = acc[mt][nt][3];
            if (EPI == EPI_HL) {
                epi_store_hl(Ch, Cl, row0, col, v0, v1, v2, v3);
            } else {
                *(float2*)(C + (size_t)row0*Dm + col)     = make_float2(v0, v1);
                *(float2*)(C + (size_t)(row0+8)*Dm + col) = make_float2(v2, v3);
            }
        }
    }
}

// ---------------- selective-WKV recurrent scan --------------------------------
// cp.async double-buffered staging + warp-shuffle partial-sum reduction.
// Thread map: ti = t&15 (row group), tj = t>>4 (col group) -> the 16 row-group
// partials for a column group live in 16 consecutive lanes; butterfly reduces.
#define CH 8
__global__ __launch_bounds__(256) void scan_kernel(
    const float* __restrict__ kA, const float* __restrict__ vA,
    const float* __restrict__ uA, const float* __restrict__ rA,
    const float* __restrict__ state0, bf16* __restrict__ oh, bf16* __restrict__ ol,
    float* __restrict__ stateF)
{
    const int bh = blockIdx.x;
    const int b  = bh >> 5;
    const int h  = bh & 31;
    const size_t base = (size_t)b * Tt * Dm + (size_t)h * HSm;

    const int t  = threadIdx.x;
    const int ti = t & 15;     // row group (consecutive lanes)
    const int tj = t >> 4;     // col group

    __shared__ float stg[2][4][CH][64];

    float S[4][4];
    const float* st0 = state0 + (size_t)bh * 4096;
    #pragma unroll
    for (int ii = 0; ii < 4; ii++) {
        float4 s4 = *(const float4*)(st0 + (ti*4+ii)*64 + tj*4);
        S[ii][0]=s4.x; S[ii][1]=s4.y; S[ii][2]=s4.z; S[ii][3]=s4.w;
    }

    const float* bases[4] = { kA + base, vA + base, uA + base, rA + base };

    const int i0 = t, i1 = t + 256;
    const int a0 = i0 >> 7, s0 = (i0 >> 4) & 7, q0 = i0 & 15;
    const int a1 = i1 >> 7, s1 = (i1 >> 4) & 7, q1 = i1 & 15;

    {
        u32 d0 = s2u(&stg[0][a0][s0][q0*4]);
        u32 d1 = s2u(&stg[0][a1][s1][q1*4]);
        CPA(d0, (const char*)(bases[a0] + (size_t)s0*Dm + q0*4));
        CPA(d1, (const char*)(bases[a1] + (size_t)s1*Dm + q1*4));
        CPCOMMIT();
    }

    for (int c = 0; c < Tt/CH; c++) {
        const int buf = c & 1;
        CPWAIT(0);
        __syncthreads();
        if (c + 1 < Tt/CH) {
            const size_t nco = (size_t)(c+1) * CH * Dm;
            u32 d0 = s2u(&stg[buf^1][a0][s0][q0*4]);
            u32 d1 = s2u(&stg[buf^1][a1][s1][q1*4]);
            CPA(d0, (const char*)(bases[a0] + nco + (size_t)s0*Dm + q0*4));
            CPA(d1, (const char*)(bases[a1] + nco + (size_t)s1*Dm + q1*4));
            CPCOMMIT();
        }

        const size_t coff = (size_t)c * CH * Dm;
        #pragma unroll
        for (int s = 0; s < CH; s++) {
            float4 k4 = *(const float4*)(&stg[buf][0][s][ti*4]);
            float4 v4 = *(const float4*)(&stg[buf][1][s][tj*4]);
            float4 u4 = *(const float4*)(&stg[buf][2][s][ti*4]);
            float4 r4 = *(const float4*)(&stg[buf][3][s][ti*4]);
            float kv[4] = {k4.x,k4.y,k4.z,k4.w};
            float uv[4] = {u4.x,u4.y,u4.z,u4.w};
            float rv[4] = {r4.x,r4.y,r4.z,r4.w};
            float vv[4] = {v4.x,v4.y,v4.z,v4.w};
            float p0=0.f,p1=0.f,p2=0.f,p3=0.f;
            #pragma unroll
            for (int ii = 0; ii < 4; ii++) {
                S[ii][0] = fmaf(uv[ii], S[ii][0], kv[ii]*vv[0]);
                S[ii][1] = fmaf(uv[ii], S[ii][1], kv[ii]*vv[1]);
                S[ii][2] = fmaf(uv[ii], S[ii][2], kv[ii]*vv[2]);
                S[ii][3] = fmaf(uv[ii], S[ii][3], kv[ii]*vv[3]);
                p0 = fmaf(rv[ii], S[ii][0], p0);
                p1 = fmaf(rv[ii], S[ii][1], p1);
                p2 = fmaf(rv[ii], S[ii][2], p2);
                p3 = fmaf(rv[ii], S[ii][3], p3);
            }
            // butterfly over the 16 row groups (lane bits 0..3)
            #pragma unroll
            for (int o = 1; o < 16; o <<= 1) {
                p0 += __shfl_xor_sync(0xffffffffu, p0, o);
                p1 += __shfl_xor_sync(0xffffffffu, p1, o);
                p2 += __shfl_xor_sync(0xffffffffu, p2, o);
                p3 += __shfl_xor_sync(0xffffffffu, p3, o);
            }
            if (ti == 0) {
                size_t idx = base + coff + (size_t)s*Dm + tj*4;
                BF2U H0, H1, L0, L1;
                H0.h = __floats2bfloat162_rn(p0, p1);
                H1.h = __floats2bfloat162_rn(p2, p3);
                L0.h = __floats2bfloat162_rn(p0 - __bfloat162float(H0.h.x),
                                             p1 - __bfloat162float(H0.h.y));
                L1.h = __floats2bfloat162_rn(p2 - __bfloat162float(H1.h.x),
                                             p3 - __bfloat162float(H1.h.y));
                uint2 Hq, Lq;
                Hq.x = H0.u; Hq.y = H1.u; Lq.x = L0.u; Lq.y = L1.u;
                *(uint2*)(oh + idx) = Hq;
                *(uint2*)(ol + idx) = Lq;
            }
        }
        __syncthreads();
    }

    float* sf = stateF + (size_t)bh * 4096;
    #pragma unroll
    for (int ii = 0; ii < 4; ii++)
        *(float4*)(sf + (ti*4+ii)*64 + tj*4)
            = make_float4(S[ii][0],S[ii][1],S[ii][2],S[ii][3]);
}

// ---------------- launch ------------------------------------------------------
extern "C" void kernel_launch(void* const* d_in, const int* in_sizes, int n_in,
                              void* d_out, int out_size)
{
    const float* x     = (const float*)d_in[0];
    const float* state = (const float*)d_in[1];
    const float* ln_g  = (const float*)d_in[2];
    const float* ln_b  = (const float*)d_in[3];
    const float* Wx    = (const float*)d_in[4];
    const float* Ww    = (const float*)d_in[5];
    const float* bw    = (const float*)d_in[6];
    const float* Wk    = (const float*)d_in[7];
    const float* Wv    = (const float*)d_in[8];
    const float* Wr    = (const float*)d_in[9];
    const float* Wo    = (const float*)d_in[10];

    float* y_out  = (float*)d_out;
    float* sf_out = (float*)d_out + YSZ;

    float *kk, *vv, *uu, *rr;
    bf16 *xnh, *xnl, *oh, *ol, *wfh, *wfl;
    bf16 *whbase, *wlbase;
    cudaGetSymbolAddress((void**)&kk,  g_k);
    cudaGetSymbolAddress((void**)&vv,  g_v);
    cudaGetSymbolAddress((void**)&uu,  g_u);
    cudaGetSymbolAddress((void**)&rr,  g_r);
    cudaGetSymbolAddress((void**)&xnh, g_xnh);
    cudaGetSymbolAddress((void**)&xnl, g_xnl);
    cudaGetSymbolAddress((void**)&oh,  g_oh);
    cudaGetSymbolAddress((void**)&ol,  g_ol);
    cudaGetSymbolAddress((void**)&wfh, g_Wfh);
    cudaGetSymbolAddress((void**)&wfl, g_Wfl);
    cudaGetSymbolAddress((void**)&whbase, g_Wh);
    cudaGetSymbolAddress((void**)&wlbase, g_Wl);
    bf16 *wh[6], *wl[6];
    for (int i = 0; i < 6; i++) { wh[i] = whbase + (size_t)i*WSZ; wl[i] = wlbase + (size_t)i*WSZ; }

    cudaFuncSetAttribute(gemm_batch,         cudaFuncAttributeMaxDynamicSharedMemorySize, SMEM_BYTES);
    cudaFuncSetAttribute(gemm_mma<EPI_HL>,   cudaFuncAttributeMaxDynamicSharedMemorySize, SMEM_BYTES);
    cudaFuncSetAttribute(gemm_mma<EPI_NONE>, cudaFuncAttributeMaxDynamicSharedMemorySize, SMEM_BYTES);

    // launch 0: weight splits (Ww,Wk,Wv,Wr,Wo normal; Wx transposed)
    {
        dim3 cg(4096, 6);
        conv_all<<<cg, 256>>>(Wx, Ww, Wk, Wv, Wr, Wo, whbase, wlbase);
    }

    // launch 1: LayerNorm -> split xn
    ln_kernel<<<MROWS, 256>>>(x, ln_g, ln_b, xnh, xnl);

    // launch 2: Wf = Ww @ Wx (split output)
    {
        dim3 gw(Dm/128, Dm/128);
        gemm_mma<EPI_HL><<<gw, 256, SMEM_BYTES>>>(wh[1], wl[1], wh[0], wl[0],
                                                  nullptr, wfh, wfl);
    }

    // launch 3: batched GEMMs over xn: Wf (USIG->u), Wk, Wv, Wr (SIG)
    {
        GSet s0 = { wfh, wfl, bw, uu, nullptr, nullptr, EPI_USIG };
        GSet s1 = { wh[2], wl[2], nullptr, kk, nullptr, nullptr, EPI_NONE };
        GSet s2 = { wh[3], wl[3], nullptr, vv, nullptr, nullptr, EPI_NONE };
        GSet s3 = { wh[4], wl[4], nullptr, rr, nullptr, nullptr, EPI_SIG };
        dim3 gg(Dm/128, MROWS/128, 4);
        gemm_batch<<<gg, 256, SMEM_BYTES>>>(xnh, xnl, s0, s1, s2, s3);
    }

    // launch 4: scan
    scan_kernel<<<Bb*Hh, 256>>>(kk, vv, uu, rr, state, oh, ol, sf_out);

    // launch 5: y = outs @ Wo^T
    {
        dim3 g1(Dm/128, MROWS/128);
        gemm_mma<EPI_NONE><<<g1, 256, SMEM_BYTES>>>(oh, ol, wh[5], wl[5],
                                                    y_out, nullptr, nullptr);
    }
}

// round 16
// speedup vs baseline: 1.0829x; 1.0706x over previous
#include <cuda_runtime.h>
#include <cuda_bf16.h>
#include <cstdint>
#include <math.h>

#define Dm   2048
#define Bb   4
#define Tt   2048
#define Hh   32
#define HSm  64
#define MROWS 8192
#define YSZ  (MROWS*Dm)
#define WSZ  (Dm*Dm)

typedef unsigned int u32;
typedef unsigned long long u64;
typedef __nv_bfloat16 bf16;

// ---------------- static device scratch --------------------------------------
__device__ float g_k[YSZ], g_v[YSZ], g_u[YSZ], g_r[YSZ];
__device__ bf16  g_xnh[YSZ], g_xnl[YSZ], g_oh[YSZ], g_ol[YSZ];
__device__ bf16  g_Wh[6][WSZ], g_Wl[6][WSZ];     // 0=Wx^T 1=Ww 2=Wk 3=Wv 4=Wr 5=Wo
__device__ bf16  g_Wfh[WSZ], g_Wfl[WSZ];         // fused Ww@Wx

// ---------------- helpers ------------------------------------------------------
#define CPA(dst,src)   asm volatile("cp.async.cg.shared.global [%0], [%1], 16;" :: "r"(dst), "l"(src))
#define CPCOMMIT()     asm volatile("cp.async.commit_group;" ::: "memory")
#define CPWAIT(n)      asm volatile("cp.async.wait_group %0;" :: "n"(n) : "memory")

__device__ __forceinline__ u32 s2u(const void* p){
    u32 a; asm("{ .reg .u64 t; cvta.to.shared.u64 t, %1; cvt.u32.u64 %0, t; }" : "=r"(a) : "l"(p)); return a;
}

__device__ __forceinline__ void mma16816(float* c, const u32* a, const u32* b){
    asm volatile("mma.sync.aligned.m16n8k16.row.col.f32.bf16.bf16.f32 "
        "{%0,%1,%2,%3}, {%4,%5,%6,%7}, {%8,%9}, {%0,%1,%2,%3};"
        : "+f"(c[0]), "+f"(c[1]), "+f"(c[2]), "+f"(c[3])
        : "r"(a[0]), "r"(a[1]), "r"(a[2]), "r"(a[3]), "r"(b[0]), "r"(b[1]));
}

// packed f32x2 (sm_100-family PTX, verified to assemble at .target sm_103 in R3)
#define FMA2(d,a,b,c) asm("fma.rn.f32x2 %0,%1,%2,%3;" : "=l"(d) : "l"(a), "l"(b), "l"(c))
#define MUL2(d,a,b)   asm("mul.rn.f32x2 %0,%1,%2;"    : "=l"(d) : "l"(a), "l"(b))
#define PK2(d,x)      asm("mov.b64 %0,{%1,%1};"       : "=l"(d) : "f"(x))
union F4U2 { float4 f; u64 u[2]; };

union BF2U { __nv_bfloat162 h; u32 u; };

__device__ __forceinline__ void split4(float4 v, uint2& H, uint2& L){
    BF2U h0, h1, l0, l1;
    h0.h = __floats2bfloat162_rn(v.x, v.y);
    h1.h = __floats2bfloat162_rn(v.z, v.w);
    float lx = v.x - __bfloat162float(h0.h.x);
    float ly = v.y - __bfloat162float(h0.h.y);
    float lz = v.z - __bfloat162float(h1.h.x);
    float lw = v.w - __bfloat162float(h1.h.y);
    l0.h = __floats2bfloat162_rn(lx, ly);
    l1.h = __floats2bfloat162_rn(lz, lw);
    H.x = h0.u; H.y = h1.u; L.x = l0.u; L.y = l1.u;
}

// ---------------- weight split (5 normal + 1 transpose in ONE launch) ---------
__global__ __launch_bounds__(256) void conv_all(
    const float* __restrict__ sWx,
    const float* __restrict__ s0, const float* __restrict__ s1,
    const float* __restrict__ s2, const float* __restrict__ s3,
    const float* __restrict__ s4,
    bf16* __restrict__ dh, bf16* __restrict__ dl)
{
    __shared__ float tile[32][33];
    const int wi = blockIdx.y;
    if (wi < 5) {
        const float* src = wi==0?s0 : wi==1?s1 : wi==2?s2 : wi==3?s3 : s4;
        int i = blockIdx.x * 256 + threadIdx.x;
        float4 v = ((const float4*)src)[i];
        uint2 H, L;
        split4(v, H, L);
        size_t o = (size_t)(wi+1) * (WSZ/4) + i;
        ((uint2*)dh)[o] = H; ((uint2*)dl)[o] = L;
    } else {
        const int bx = (blockIdx.x & 63) * 32;
        const int by = (blockIdx.x >> 6) * 32;
        const int tx = threadIdx.x & 31, ty = threadIdx.x >> 5;
        #pragma unroll
        for (int i = 0; i < 32; i += 8)
            tile[ty+i][tx] = sWx[(size_t)(by+ty+i)*Dm + bx+tx];
        __syncthreads();
        #pragma unroll
        for (int i = 0; i < 32; i += 8) {
            float v = tile[tx][ty+i];
            bf16 h = __float2bfloat16(v);
            bf16 l = __float2bfloat16(v - __bfloat162float(h));
            size_t o = (size_t)(bx+ty+i)*Dm + (by+tx);
            dh[o] = h; dl[o] = l;
        }
    }
}

// ---------------- LayerNorm -> hi/lo bf16 -------------------------------------
__global__ __launch_bounds__(256) void ln_kernel(
    const float* __restrict__ x, const float* __restrict__ gam,
    const float* __restrict__ bet, bf16* __restrict__ oh, bf16* __restrict__ ol)
{
    __shared__ float red[18];
    const int row = blockIdx.x;
    const int t = threadIdx.x;
    const float* xr = x + (size_t)row * Dm;

    float4 a0 = *(const float4*)(xr + 4*t);
    float4 a1 = *(const float4*)(xr + 1024 + 4*t);
    float s  = a0.x+a0.y+a0.z+a0.w + a1.x+a1.y+a1.z+a1.w;
    float ss = a0.x*a0.x+a0.y*a0.y+a0.z*a0.z+a0.w*a0.w
             + a1.x*a1.x+a1.y*a1.y+a1.z*a1.z+a1.w*a1.w;
    #pragma unroll
    for (int o = 16; o; o >>= 1) {
        s  += __shfl_xor_sync(0xffffffffu, s,  o);
        ss += __shfl_xor_sync(0xffffffffu, ss, o);
    }
    if ((t & 31) == 0) { red[t>>5] = s; red[8 + (t>>5)] = ss; }
    __syncthreads();
    if (t == 0) {
        float S = 0.f, SS = 0.f;
        #pragma unroll
        for (int i = 0; i < 8; i++) { S += red[i]; SS += red[8+i]; }
        float mu  = S * (1.0f/Dm);
        float var = SS * (1.0f/Dm) - mu*mu;
        red[16] = mu;
        red[17] = rsqrtf(var + 1e-5f);
    }
    __syncthreads();
    const float mu = red[16], rstd = red[17];

    float4 g0 = *(const float4*)(gam + 4*t);
    float4 g1 = *(const float4*)(gam + 1024 + 4*t);
    float4 b0 = *(const float4*)(bet + 4*t);
    float4 b1 = *(const float4*)(bet + 1024 + 4*t);
    float4 r0, r1;
    r0.x = (a0.x - mu)*rstd*g0.x + b0.x;
    r0.y = (a0.y - mu)*rstd*g0.y + b0.y;
    r0.z = (a0.z - mu)*rstd*g0.z + b0.z;
    r0.w = (a0.w - mu)*rstd*g0.w + b0.w;
    r1.x = (a1.x - mu)*rstd*g1.x + b1.x;
    r1.y = (a1.y - mu)*rstd*g1.y + b1.y;
    r1.z = (a1.z - mu)*rstd*g1.z + b1.z;
    r1.w = (a1.w - mu)*rstd*g1.w + b1.w;

    uint2 H, L;
    const size_t o0 = (size_t)row * Dm + 4*t;
    split4(r0, H, L);
    *(uint2*)(oh + o0) = H; *(uint2*)(ol + o0) = L;
    split4(r1, H, L);
    *(uint2*)(oh + o0 + 1024) = H; *(uint2*)(ol + o0 + 1024) = L;
}

// ---------------- split-bf16 mma.sync GEMM core (R13 proven config) -----------
#define OFF(tile,buf) ((buf)*40960u + (tile)*10240u)   // AH=0 AL=1 BH=2 BL=3
#define SMEM_BYTES 81920

#define EPI_NONE 0
#define EPI_SIG  1
#define EPI_USIG 2
#define EPI_HL   3

__device__ __forceinline__ void load_tiles(
    u32 sb, int buf, int t,
    const bf16* Ah, const bf16* Al, const bf16* Bh, const bf16* Bl,
    size_t arow, size_t brow, int k0)
{
    #pragma unroll
    for (int p = 0; p < 2; p++) {
        int i = t + p*256;
        int r = i >> 2, c16 = i & 3;
        u32 dst = (u32)(r*80 + c16*16);
        size_t go = (size_t)r*Dm + k0 + c16*8;
        CPA(sb + OFF(0,buf) + dst, (const char*)(Ah + arow + go));
        CPA(sb + OFF(1,buf) + dst, (const char*)(Al + arow + go));
        CPA(sb + OFF(2,buf) + dst, (const char*)(Bh + brow + go));
        CPA(sb + OFF(3,buf) + dst, (const char*)(Bl + brow + go));
    }
}

__device__ __forceinline__ void gemm_chunk(
    const bf16* sAh, const bf16* sAl, const bf16* sBh, const bf16* sBl,
    int wm, int wn, int lq, int lr, float (&acc)[4][4][4])
{
    #pragma unroll
    for (int ks = 0; ks < 2; ks++) {
        const int kofs = ks*16 + lr*2;
        u32 bh[4][2], bl[4][2];
        #pragma unroll
        for (int nt = 0; nt < 4; nt++) {
            int n0 = wn*32 + nt*8 + lq;
            bh[nt][0] = *(const u32*)(sBh + n0*40 + kofs);
            bh[nt][1] = *(const u32*)(sBh + n0*40 + kofs + 8);
            bl[nt][0] = *(const u32*)(sBl + n0*40 + kofs);
            bl[nt][1] = *(const u32*)(sBl + n0*40 + kofs + 8);
        }
        #pragma unroll
        for (int mt = 0; mt < 4; mt++) {
            int r0 = wm*64 + mt*16 + lq;
            u32 ah[4], al[4];
            ah[0] = *(const u32*)(sAh + r0*40 + kofs);
            ah[1] = *(const u32*)(sAh + (r0+8)*40 + kofs);
            ah[2] = *(const u32*)(sAh + r0*40 + kofs + 8);
            ah[3] = *(const u32*)(sAh + (r0+8)*40 + kofs + 8);
            al[0] = *(const u32*)(sAl + r0*40 + kofs);
            al[1] = *(const u32*)(sAl + (r0+8)*40 + kofs);
            al[2] = *(const u32*)(sAl + r0*40 + kofs + 8);
            al[3] = *(const u32*)(sAl + (r0+8)*40 + kofs + 8);
            #pragma unroll
            for (int nt = 0; nt < 4; nt++) {
                mma16816(acc[mt][nt], ah, bh[nt]);
                mma16816(acc[mt][nt], ah, bl[nt]);
                mma16816(acc[mt][nt], al, bh[nt]);
            }
        }
    }
}

__device__ __forceinline__ void epi_store_hl(
    bf16* Ch, bf16* Cl, int row0, int col, float v0, float v1, float v2, float v3)
{
    BF2U H0, H1, L0, L1;
    H0.h = __floats2bfloat162_rn(v0, v1);
    H1.h = __floats2bfloat162_rn(v2, v3);
    L0.h = __floats2bfloat162_rn(v0 - __bfloat162float(H0.h.x),
                                 v1 - __bfloat162float(H0.h.y));
    L1.h = __floats2bfloat162_rn(v2 - __bfloat162float(H1.h.x),
                                 v3 - __bfloat162float(H1.h.y));
    *(u32*)(Ch + (size_t)row0*Dm + col)     = H0.u;
    *(u32*)(Ch + (size_t)(row0+8)*Dm + col) = H1.u;
    *(u32*)(Cl + (size_t)row0*Dm + col)     = L0.u;
    *(u32*)(Cl + (size_t)(row0+8)*Dm + col) = L1.u;
}

// ---- batched GEMM over 4 weight sets (shared A), blockIdx.z selects set -----
struct GSet {
    const bf16* Bh; const bf16* Bl; const float* bias;
    float* C; bf16* Ch; bf16* Cl;
    int epi;
};

__global__ __launch_bounds__(256, 2) void gemm_batch(
    const bf16* __restrict__ Ah, const bf16* __restrict__ Al,
    GSet g0, GSet g1, GSet g2, GSet g3)
{
    extern __shared__ char sm[];
    const u32 sb = s2u(sm);
    const int t = threadIdx.x;
    const int w = t >> 5, lane = t & 31;
    const int wm = w >> 2, wn = w & 3;
    const int bn = blockIdx.x, bm = blockIdx.y, z = blockIdx.z;

    const bf16* Bh = (z==0) ? g0.Bh : (z==1) ? g1.Bh : (z==2) ? g2.Bh : g3.Bh;
    const bf16* Bl = (z==0) ? g0.Bl : (z==1) ? g1.Bl : (z==2) ? g2.Bl : g3.Bl;

    const size_t arow = (size_t)bm * 128 * Dm;
    const size_t brow = (size_t)bn * 128 * Dm;

    float acc[4][4][4];
    #pragma unroll
    for (int i = 0; i < 4; i++)
        #pragma unroll
        for (int j = 0; j < 4; j++)
            #pragma unroll
            for (int q = 0; q < 4; q++) acc[i][j][q] = 0.f;

    load_tiles(sb, 0, t, Ah, Al, Bh, Bl, arow, brow, 0);
    CPCOMMIT();

    const int lq = lane >> 2;
    const int lr = lane & 3;

    for (int c = 0; c < 64; c++) {
        const int buf = c & 1;
        CPWAIT(0);
        __syncthreads();
        if (c + 1 < 64) {
            load_tiles(sb, buf ^ 1, t, Ah, Al, Bh, Bl, arow, brow, (c+1)*32);
            CPCOMMIT();
        }
        gemm_chunk((const bf16*)(sm + OFF(0,buf)), (const bf16*)(sm + OFF(1,buf)),
                   (const bf16*)(sm + OFF(2,buf)), (const bf16*)(sm + OFF(3,buf)),
                   wm, wn, lq, lr, acc);
    }

    GSet gs = (z==0) ? g0 : (z==1) ? g1 : (z==2) ? g2 : g3;
    #pragma unroll
    for (int mt = 0; mt < 4; mt++) {
        #pragma unroll
        for (int nt = 0; nt < 4; nt++) {
            int row0 = bm*128 + wm*64 + mt*16 + lq;
            int col  = bn*128 + wn*32 + nt*8 + lr*2;
            float v0 = acc[mt][nt][0], v1 = acc[mt][nt][1];
            float v2 = acc[mt][nt][2], v3 = acc[mt][nt][3];
            if (gs.epi == EPI_SIG) {
                v0 = 1.0f/(1.0f+__expf(-v0)); v1 = 1.0f/(1.0f+__expf(-v1));
                v2 = 1.0f/(1.0f+__expf(-v2)); v3 = 1.0f/(1.0f+__expf(-v3));
            }
            if (gs.epi == EPI_USIG) {
                float bb0 = __ldg(gs.bias + col), bb1 = __ldg(gs.bias + col + 1);
                v0 = 1.0f/(1.0f+__expf(v0+bb0)); v1 = 1.0f/(1.0f+__expf(v1+bb1));
                v2 = 1.0f/(1.0f+__expf(v2+bb0)); v3 = 1.0f/(1.0f+__expf(v3+bb1));
            }
            if (gs.epi == EPI_HL) {
                epi_store_hl(gs.Ch, gs.Cl, row0, col, v0, v1, v2, v3);
            } else {
                *(float2*)(gs.C + (size_t)row0*Dm + col)     = make_float2(v0, v1);
                *(float2*)(gs.C + (size_t)(row0+8)*Dm + col) = make_float2(v2, v3);
            }
        }
    }
}

// ---- single GEMM (templated epilogue): Wf weight-fuse (HL) and Wo (NONE) -----
template<int EPI>
__global__ __launch_bounds__(256, 2) void gemm_mma(
    const bf16* __restrict__ Ah, const bf16* __restrict__ Al,
    const bf16* __restrict__ Bh, const bf16* __restrict__ Bl,
    float* __restrict__ C, bf16* __restrict__ Ch, bf16* __restrict__ Cl)
{
    extern __shared__ char sm[];
    const u32 sb = s2u(sm);
    const int t = threadIdx.x;
    const int w = t >> 5, lane = t & 31;
    const int wm = w >> 2, wn = w & 3;
    const int bn = blockIdx.x, bm = blockIdx.y;

    const size_t arow = (size_t)bm * 128 * Dm;
    const size_t brow = (size_t)bn * 128 * Dm;

    float acc[4][4][4];
    #pragma unroll
    for (int i = 0; i < 4; i++)
        #pragma unroll
        for (int j = 0; j < 4; j++)
            #pragma unroll
            for (int q = 0; q < 4; q++) acc[i][j][q] = 0.f;

    load_tiles(sb, 0, t, Ah, Al, Bh, Bl, arow, brow, 0);
    CPCOMMIT();

    const int lq = lane >> 2;
    const int lr = lane & 3;

    for (int c = 0; c < 64; c++) {
        const int buf = c & 1;
        CPWAIT(0);
        __syncthreads();
        if (c + 1 < 64) {
            load_tiles(sb, buf ^ 1, t, Ah, Al, Bh, Bl, arow, brow, (c+1)*32);
            CPCOMMIT();
        }
        gemm_chunk((const bf16*)(sm + OFF(0,buf)), (const bf16*)(sm + OFF(1,buf)),
                   (const bf16*)(sm + OFF(2,buf)), (const bf16*)(sm + OFF(3,buf)),
                   wm, wn, lq, lr, acc);
    }

    #pragma unroll
    for (int mt = 0; mt < 4; mt++) {
        #pragma unroll
        for (int nt = 0; nt < 4; nt++) {
            int row0 = bm*128 + wm*64 + mt*16 + lq;
            int col  = bn*128 + wn*32 + nt*8 + lr*2;
            float v0 = acc[mt][nt][0], v1 = acc[mt][nt][1];
            float v2 = acc[mt][nt][2], v3 = acc[mt][nt][3];
            if (EPI == EPI_HL) {
                epi_store_hl(Ch, Cl, row0, col, v0, v1, v2, v3);
            } else {
                *(float2*)(C + (size_t)row0*Dm + col)     = make_float2(v0, v1);
                *(float2*)(C + (size_t)(row0+8)*Dm + col) = make_float2(v2, v3);
            }
        }
    }
}

// ---------------- selective-WKV recurrent scan --------------------------------
// R13 structure (smem partial-sum reduction) with packed f32x2 inner math.
#define CH 8
__global__ __launch_bounds__(256) void scan_kernel(
    const float* __restrict__ kA, const float* __restrict__ vA,
    const float* __restrict__ uA, const float* __restrict__ rA,
    const float* __restrict__ state0, bf16* __restrict__ oh, bf16* __restrict__ ol,
    float* __restrict__ stateF)
{
    const int bh = blockIdx.x;
    const int b  = bh >> 5;
    const int h  = bh & 31;
    const size_t base = (size_t)b * Tt * Dm + (size_t)h * HSm;

    const int t  = threadIdx.x;
    const int ti = t >> 4;
    const int tj = t & 15;

    __shared__ float stg[2][4][CH][64];
    __shared__ float pS[CH][16][64];

    u64 S2[4][2];
    const float* st0 = state0 + (size_t)bh * 4096;
    #pragma unroll
    for (int ii = 0; ii < 4; ii++) {
        F4U2 sv; sv.f = *(const float4*)(st0 + (ti*4+ii)*64 + tj*4);
        S2[ii][0] = sv.u[0]; S2[ii][1] = sv.u[1];
    }

    const float* bases[4] = { kA + base, vA + base, uA + base, rA + base };

    const int i0 = t, i1 = t + 256;
    const int a0 = i0 >> 7, s0 = (i0 >> 4) & 7, q0 = i0 & 15;
    const int a1 = i1 >> 7, s1 = (i1 >> 4) & 7, q1 = i1 & 15;

    {
        u32 d0 = s2u(&stg[0][a0][s0][q0*4]);
        u32 d1 = s2u(&stg[0][a1][s1][q1*4]);
        CPA(d0, (const char*)(bases[a0] + (size_t)s0*Dm + q0*4));
        CPA(d1, (const char*)(bases[a1] + (size_t)s1*Dm + q1*4));
        CPCOMMIT();
    }

    for (int c = 0; c < Tt/CH; c++) {
        const int buf = c & 1;
        CPWAIT(0);
        __syncthreads();
        if (c + 1 < Tt/CH) {
            const size_t nco = (size_t)(c+1) * CH * Dm;
            u32 d0 = s2u(&stg[buf^1][a0][s0][q0*4]);
            u32 d1 = s2u(&stg[buf^1][a1][s1][q1*4]);
            CPA(d0, (const char*)(bases[a0] + nco + (size_t)s0*Dm + q0*4));
            CPA(d1, (const char*)(bases[a1] + nco + (size_t)s1*Dm + q1*4));
            CPCOMMIT();
        }

        #pragma unroll
        for (int s = 0; s < CH; s++) {
            float4 k4 = *(const float4*)(&stg[buf][0][s][ti*4]);
            float4 u4 = *(const float4*)(&stg[buf][2][s][ti*4]);
            float4 r4 = *(const float4*)(&stg[buf][3][s][ti*4]);
            F4U2 vv;  vv.f = *(const float4*)(&stg[buf][1][s][tj*4]);
            float ka[4] = {k4.x,k4.y,k4.z,k4.w};
            float ua[4] = {u4.x,u4.y,u4.z,u4.w};
            float ra[4] = {r4.x,r4.y,r4.z,r4.w};
            u64 p0 = 0ull, p1 = 0ull;
            #pragma unroll
            for (int ii = 0; ii < 4; ii++) {
                u64 kp, up, rp, t0, t1;
                PK2(kp, ka[ii]); PK2(up, ua[ii]); PK2(rp, ra[ii]);
                MUL2(t0, kp, vv.u[0]);
                MUL2(t1, kp, vv.u[1]);
                FMA2(S2[ii][0], up, S2[ii][0], t0);
                FMA2(S2[ii][1], up, S2[ii][1], t1);
                FMA2(p0, rp, S2[ii][0], p0);
                FMA2(p1, rp, S2[ii][1], p1);
            }
            F4U2 ps; ps.u[0] = p0; ps.u[1] = p1;
            *(float4*)(&pS[s][ti][tj*4]) = ps.f;
        }
        __syncthreads();

        const size_t coff = (size_t)c * CH * Dm;
        #pragma unroll
        for (int q = 0; q < 2; q++) {
            int o = t + q*256;
            int s = o >> 6;
            int j = o & 63;
            float sum = 0.f;
            #pragma unroll
            for (int ii = 0; ii < 16; ii++) sum += pS[s][ii][j];
            size_t idx = base + coff + (size_t)s*Dm + j;
            bf16 hv = __float2bfloat16(sum);
            oh[idx] = hv;
            ol[idx] = __float2bfloat16(sum - __bfloat162float(hv));
        }
        __syncthreads();
    }

    float* sf = stateF + (size_t)bh * 4096;
    #pragma unroll
    for (int ii = 0; ii < 4; ii++) {
        F4U2 sv; sv.u[0] = S2[ii][0]; sv.u[1] = S2[ii][1];
        *(float4*)(sf + (ti*4+ii)*64 + tj*4) = sv.f;
    }
}

// ---------------- launch ------------------------------------------------------
extern "C" void kernel_launch(void* const* d_in, const int* in_sizes, int n_in,
                              void* d_out, int out_size)
{
    const float* x     = (const float*)d_in[0];
    const float* state = (const float*)d_in[1];
    const float* ln_g  = (const float*)d_in[2];
    const float* ln_b  = (const float*)d_in[3];
    const float* Wx    = (const float*)d_in[4];
    const float* Ww    = (const float*)d_in[5];
    const float* bw    = (const float*)d_in[6];
    const float* Wk    = (const float*)d_in[7];
    const float* Wv    = (const float*)d_in[8];
    const float* Wr    = (const float*)d_in[9];
    const float* Wo    = (const float*)d_in[10];

    float* y_out  = (float*)d_out;
    float* sf_out = (float*)d_out + YSZ;

    float *kk, *vv, *uu, *rr;
    bf16 *xnh, *xnl, *oh, *ol, *wfh, *wfl;
    bf16 *whbase, *wlbase;
    cudaGetSymbolAddress((void**)&kk,  g_k);
    cudaGetSymbolAddress((void**)&vv,  g_v);
    cudaGetSymbolAddress((void**)&uu,  g_u);
    cudaGetSymbolAddress((void**)&rr,  g_r);
    cudaGetSymbolAddress((void**)&xnh, g_xnh);
    cudaGetSymbolAddress((void**)&xnl, g_xnl);
    cudaGetSymbolAddress((void**)&oh,  g_oh);
    cudaGetSymbolAddress((void**)&ol,  g_ol);
    cudaGetSymbolAddress((void**)&wfh, g_Wfh);
    cudaGetSymbolAddress((void**)&wfl, g_Wfl);
    cudaGetSymbolAddress((void**)&whbase, g_Wh);
    cudaGetSymbolAddress((void**)&wlbase, g_Wl);
    bf16 *wh[6], *wl[6];
    for (int i = 0; i < 6; i++) { wh[i] = whbase + (size_t)i*WSZ; wl[i] = wlbase + (size_t)i*WSZ; }

    cudaFuncSetAttribute(gemm_batch,         cudaFuncAttributeMaxDynamicSharedMemorySize, SMEM_BYTES);
    cudaFuncSetAttribute(gemm_mma<EPI_HL>,   cudaFuncAttributeMaxDynamicSharedMemorySize, SMEM_BYTES);
    cudaFuncSetAttribute(gemm_mma<EPI_NONE>, cudaFuncAttributeMaxDynamicSharedMemorySize, SMEM_BYTES);

    // launch 0: weight splits (Ww,Wk,Wv,Wr,Wo normal; Wx transposed)
    {
        dim3 cg(4096, 6);
        conv_all<<<cg, 256>>>(Wx, Ww, Wk, Wv, Wr, Wo, whbase, wlbase);
    }

    // launch 1: LayerNorm -> split xn
    ln_kernel<<<MROWS, 256>>>(x, ln_g, ln_b, xnh, xnl);

    // launch 2: Wf = Ww @ Wx (split output)
    {
        dim3 gw(Dm/128, Dm/128);
        gemm_mma<EPI_HL><<<gw, 256, SMEM_BYTES>>>(wh[1], wl[1], wh[0], wl[0],
                                                  nullptr, wfh, wfl);
    }

    // launch 3: batched GEMMs over xn: Wf (USIG->u), Wk, Wv, Wr (SIG)
    {
        GSet s0 = { wfh, wfl, bw, uu, nullptr, nullptr, EPI_USIG };
        GSet s1 = { wh[2], wl[2], nullptr, kk, nullptr, nullptr, EPI_NONE };
        GSet s2 = { wh[3], wl[3], nullptr, vv, nullptr, nullptr, EPI_NONE };
        GSet s3 = { wh[4], wl[4], nullptr, rr, nullptr, nullptr, EPI_SIG };
        dim3 gg(Dm/128, MROWS/128, 4);
        gemm_batch<<<gg, 256, SMEM_BYTES>>>(xnh, xnl, s0, s1, s2, s3);
    }

    // launch 4: scan
    scan_kernel<<<Bb*Hh, 256>>>(kk, vv, uu, rr, state, oh, ol, sf_out);

    // launch 5: y = outs @ Wo^T
    {
        dim3 g1(Dm/128, MROWS/128);
        gemm_mma<EPI_NONE><<<g1, 256, SMEM_BYTES>>>(oh, ol, wh[5], wl[5],
                                                    y_out, nullptr, nullptr);
    }
}

// round 17
// speedup vs baseline: 1.3812x; 1.2755x over previous
#include <cuda_runtime.h>
#include <cuda_bf16.h>
#include <cuda_fp16.h>
#include <cstdint>
#include <math.h>

#define Dm   2048
#define Bb   4
#define Tt   2048
#define Hh   32
#define HSm  64
#define MROWS 8192
#define YSZ  (MROWS*Dm)
#define WSZ  (Dm*Dm)

typedef unsigned int u32;
typedef unsigned long long u64;
typedef __nv_bfloat16 bf16;
typedef __half f16;

// ---------------- static device scratch --------------------------------------
__device__ float g_k[YSZ], g_v[YSZ], g_u[YSZ], g_r[YSZ];
__device__ f16   g_xn[YSZ];
__device__ bf16  g_oh[YSZ], g_ol[YSZ];
__device__ bf16  g_Wh[3][WSZ], g_Wl[3][WSZ];     // 0=Wx^T 1=Ww 2=Wo (bf16 split)
__device__ f16   g_Fh[4][WSZ], g_Fl[4][WSZ];     // 0=Wk 1=Wv 2=Wr 3=Wf (fp16 split)

// ---------------- helpers ------------------------------------------------------
#define CPA(dst,src)   asm volatile("cp.async.cg.shared.global [%0], [%1], 16;" :: "r"(dst), "l"(src))
#define CPCOMMIT()     asm volatile("cp.async.commit_group;" ::: "memory")
#define CPWAIT(n)      asm volatile("cp.async.wait_group %0;" :: "n"(n) : "memory")

__device__ __forceinline__ u32 s2u(const void* p){
    u32 a; asm("{ .reg .u64 t; cvta.to.shared.u64 t, %1; cvt.u32.u64 %0, t; }" : "=r"(a) : "l"(p)); return a;
}

__device__ __forceinline__ void mma_bf16(float* c, const u32* a, const u32* b){
    asm volatile("mma.sync.aligned.m16n8k16.row.col.f32.bf16.bf16.f32 "
        "{%0,%1,%2,%3}, {%4,%5,%6,%7}, {%8,%9}, {%0,%1,%2,%3};"
        : "+f"(c[0]), "+f"(c[1]), "+f"(c[2]), "+f"(c[3])
        : "r"(a[0]), "r"(a[1]), "r"(a[2]), "r"(a[3]), "r"(b[0]), "r"(b[1]));
}
__device__ __forceinline__ void mma_f16(float* c, const u32* a, const u32* b){
    asm volatile("mma.sync.aligned.m16n8k16.row.col.f32.f16.f16.f32 "
        "{%0,%1,%2,%3}, {%4,%5,%6,%7}, {%8,%9}, {%0,%1,%2,%3};"
        : "+f"(c[0]), "+f"(c[1]), "+f"(c[2]), "+f"(c[3])
        : "r"(a[0]), "r"(a[1]), "r"(a[2]), "r"(a[3]), "r"(b[0]), "r"(b[1]));
}

// packed f32x2
#define FMA2(d,a,b,c) asm("fma.rn.f32x2 %0,%1,%2,%3;" : "=l"(d) : "l"(a), "l"(b), "l"(c))
#define MUL2(d,a,b)   asm("mul.rn.f32x2 %0,%1,%2;"    : "=l"(d) : "l"(a), "l"(b))
#define PK2(d,x)      asm("mov.b64 %0,{%1,%1};"       : "=l"(d) : "f"(x))
union F4U2 { float4 f; u64 u[2]; };

union BF2U { __nv_bfloat162 h; u32 u; };
union HF2U { __half2 h; u32 u; };

__device__ __forceinline__ void split4(float4 v, uint2& H, uint2& L){
    BF2U h0, h1, l0, l1;
    h0.h = __floats2bfloat162_rn(v.x, v.y);
    h1.h = __floats2bfloat162_rn(v.z, v.w);
    float lx = v.x - __bfloat162float(h0.h.x);
    float ly = v.y - __bfloat162float(h0.h.y);
    float lz = v.z - __bfloat162float(h1.h.x);
    float lw = v.w - __bfloat162float(h1.h.y);
    l0.h = __floats2bfloat162_rn(lx, ly);
    l1.h = __floats2bfloat162_rn(lz, lw);
    H.x = h0.u; H.y = h1.u; L.x = l0.u; L.y = l1.u;
}

__device__ __forceinline__ void splith4(float4 v, uint2& H, uint2& L){
    HF2U h0, h1, l0, l1;
    h0.h = __floats2half2_rn(v.x, v.y);
    h1.h = __floats2half2_rn(v.z, v.w);
    float lx = v.x - __half2float(__low2half(h0.h));
    float ly = v.y - __half2float(__high2half(h0.h));
    float lz = v.z - __half2float(__low2half(h1.h));
    float lw = v.w - __half2float(__high2half(h1.h));
    l0.h = __floats2half2_rn(lx, ly);
    l1.h = __floats2half2_rn(lz, lw);
    H.x = h0.u; H.y = h1.u; L.x = l0.u; L.y = l1.u;
}

// ---------------- weight prep (ONE launch, blockIdx.y selects task) ----------
// 0: Ww->bf16 slot1  1: Wo->bf16 slot2  2..4: Wk,Wv,Wr->fp16 F0..F2  5: Wx^T->bf16 slot0
__global__ __launch_bounds__(256) void conv_all(
    const float* __restrict__ sWx, const float* __restrict__ sWw,
    const float* __restrict__ sWo, const float* __restrict__ sWk,
    const float* __restrict__ sWv, const float* __restrict__ sWr,
    bf16* __restrict__ bh, bf16* __restrict__ bl,
    f16* __restrict__ fh, f16* __restrict__ fl)
{
    __shared__ float tile[32][33];
    const int wi = blockIdx.y;
    if (wi < 2) {
        const float* src = wi==0 ? sWw : sWo;
        int i = blockIdx.x * 256 + threadIdx.x;
        float4 v = ((const float4*)src)[i];
        uint2 H, L;
        split4(v, H, L);
        size_t o = (size_t)(wi+1) * (WSZ/4) + i;
        ((uint2*)bh)[o] = H; ((uint2*)bl)[o] = L;
    } else if (wi < 5) {
        const float* src = wi==2 ? sWk : wi==3 ? sWv : sWr;
        int i = blockIdx.x * 256 + threadIdx.x;
        float4 v = ((const float4*)src)[i];
        uint2 H, L;
        splith4(v, H, L);
        size_t o = (size_t)(wi-2) * (WSZ/4) + i;
        ((uint2*)fh)[o] = H; ((uint2*)fl)[o] = L;
    } else {
        const int bx = (blockIdx.x & 63) * 32;
        const int by = (blockIdx.x >> 6) * 32;
        const int tx = threadIdx.x & 31, ty = threadIdx.x >> 5;
        #pragma unroll
        for (int i = 0; i < 32; i += 8)
            tile[ty+i][tx] = sWx[(size_t)(by+ty+i)*Dm + bx+tx];
        __syncthreads();
        #pragma unroll
        for (int i = 0; i < 32; i += 8) {
            float v = tile[tx][ty+i];
            bf16 h = __float2bfloat16(v);
            bf16 l = __float2bfloat16(v - __bfloat162float(h));
            size_t o = (size_t)(bx+ty+i)*Dm + (by+tx);
            bh[o] = h; bl[o] = l;
        }
    }
}

// ---------------- LayerNorm -> single fp16 ------------------------------------
__global__ __launch_bounds__(256) void ln_kernel(
    const float* __restrict__ x, const float* __restrict__ gam,
    const float* __restrict__ bet, f16* __restrict__ oq)
{
    __shared__ float red[18];
    const int row = blockIdx.x;
    const int t = threadIdx.x;
    const float* xr = x + (size_t)row * Dm;

    float4 a0 = *(const float4*)(xr + 4*t);
    float4 a1 = *(const float4*)(xr + 1024 + 4*t);
    float s  = a0.x+a0.y+a0.z+a0.w + a1.x+a1.y+a1.z+a1.w;
    float ss = a0.x*a0.x+a0.y*a0.y+a0.z*a0.z+a0.w*a0.w
             + a1.x*a1.x+a1.y*a1.y+a1.z*a1.z+a1.w*a1.w;
    #pragma unroll
    for (int o = 16; o; o >>= 1) {
        s  += __shfl_xor_sync(0xffffffffu, s,  o);
        ss += __shfl_xor_sync(0xffffffffu, ss, o);
    }
    if ((t & 31) == 0) { red[t>>5] = s; red[8 + (t>>5)] = ss; }
    __syncthreads();
    if (t == 0) {
        float S = 0.f, SS = 0.f;
        #pragma unroll
        for (int i = 0; i < 8; i++) { S += red[i]; SS += red[8+i]; }
        float mu  = S * (1.0f/Dm);
        float var = SS * (1.0f/Dm) - mu*mu;
        red[16] = mu;
        red[17] = rsqrtf(var + 1e-5f);
    }
    __syncthreads();
    const float mu = red[16], rstd = red[17];

    float4 g0 = *(const float4*)(gam + 4*t);
    float4 g1 = *(const float4*)(gam + 1024 + 4*t);
    float4 b0 = *(const float4*)(bet + 4*t);
    float4 b1 = *(const float4*)(bet + 1024 + 4*t);
    HF2U q0, q1, q2, q3;
    q0.h = __floats2half2_rn((a0.x - mu)*rstd*g0.x + b0.x, (a0.y - mu)*rstd*g0.y + b0.y);
    q1.h = __floats2half2_rn((a0.z - mu)*rstd*g0.z + b0.z, (a0.w - mu)*rstd*g0.w + b0.w);
    q2.h = __floats2half2_rn((a1.x - mu)*rstd*g1.x + b1.x, (a1.y - mu)*rstd*g1.y + b1.y);
    q3.h = __floats2half2_rn((a1.z - mu)*rstd*g1.z + b1.z, (a1.w - mu)*rstd*g1.w + b1.w);
    const size_t o0 = (size_t)row * Dm + 4*t;
    uint2 P0; P0.x = q0.u; P0.y = q1.u;
    uint2 P1; P1.x = q2.u; P1.y = q3.u;
    *(uint2*)(oq + o0)        = P0;
    *(uint2*)(oq + o0 + 1024) = P1;
}

// ---------------- common GEMM bits --------------------------------------------
#define EPI_NONE 0
#define EPI_SIG  1
#define EPI_USIG 2
#define EPI_HLF  3   // write fp16 hi/lo (Wf output)

// ================= bf16 3-term GEMM (R13 proven) — Wf and Wo ==================
#define OFF(tile,buf) ((buf)*40960u + (tile)*10240u)   // AH=0 AL=1 BH=2 BL=3
#define SMEM_BF 81920

__device__ __forceinline__ void load_tiles_bf(
    u32 sb, int buf, int t,
    const bf16* Ah, const bf16* Al, const bf16* Bh, const bf16* Bl,
    size_t arow, size_t brow, int k0)
{
    #pragma unroll
    for (int p = 0; p < 2; p++) {
        int i = t + p*256;
        int r = i >> 2, c16 = i & 3;
        u32 dst = (u32)(r*80 + c16*16);
        size_t go = (size_t)r*Dm + k0 + c16*8;
        CPA(sb + OFF(0,buf) + dst, (const char*)(Ah + arow + go));
        CPA(sb + OFF(1,buf) + dst, (const char*)(Al + arow + go));
        CPA(sb + OFF(2,buf) + dst, (const char*)(Bh + brow + go));
        CPA(sb + OFF(3,buf) + dst, (const char*)(Bl + brow + go));
    }
}

__device__ __forceinline__ void gemm_chunk_bf(
    const bf16* sAh, const bf16* sAl, const bf16* sBh, const bf16* sBl,
    int wm, int wn, int lq, int lr, float (&acc)[4][4][4])
{
    #pragma unroll
    for (int ks = 0; ks < 2; ks++) {
        const int kofs = ks*16 + lr*2;
        u32 bh[4][2], bl[4][2];
        #pragma unroll
        for (int nt = 0; nt < 4; nt++) {
            int n0 = wn*32 + nt*8 + lq;
            bh[nt][0] = *(const u32*)(sBh + n0*40 + kofs);
            bh[nt][1] = *(const u32*)(sBh + n0*40 + kofs + 8);
            bl[nt][0] = *(const u32*)(sBl + n0*40 + kofs);
            bl[nt][1] = *(const u32*)(sBl + n0*40 + kofs + 8);
        }
        #pragma unroll
        for (int mt = 0; mt < 4; mt++) {
            int r0 = wm*64 + mt*16 + lq;
            u32 ah[4], al[4];
            ah[0] = *(const u32*)(sAh + r0*40 + kofs);
            ah[1] = *(const u32*)(sAh + (r0+8)*40 + kofs);
            ah[2] = *(const u32*)(sAh + r0*40 + kofs + 8);
            ah[3] = *(const u32*)(sAh + (r0+8)*40 + kofs + 8);
            al[0] = *(const u32*)(sAl + r0*40 + kofs);
            al[1] = *(const u32*)(sAl + (r0+8)*40 + kofs);
            al[2] = *(const u32*)(sAl + r0*40 + kofs + 8);
            al[3] = *(const u32*)(sAl + (r0+8)*40 + kofs + 8);
            #pragma unroll
            for (int nt = 0; nt < 4; nt++) {
                mma_bf16(acc[mt][nt], ah, bh[nt]);
                mma_bf16(acc[mt][nt], ah, bl[nt]);
                mma_bf16(acc[mt][nt], al, bh[nt]);
            }
        }
    }
}

__device__ __forceinline__ void epi_store_hlf(
    f16* Ch, f16* Cl, int row0, int col, float v0, float v1, float v2, float v3)
{
    HF2U H0, H1, L0, L1;
    H0.h = __floats2half2_rn(v0, v1);
    H1.h = __floats2half2_rn(v2, v3);
    L0.h = __floats2half2_rn(v0 - __half2float(__low2half(H0.h)),
                             v1 - __half2float(__high2half(H0.h)));
    L1.h = __floats2half2_rn(v2 - __half2float(__low2half(H1.h)),
                             v3 - __half2float(__high2half(H1.h)));
    *(u32*)(Ch + (size_t)row0*Dm + col)     = H0.u;
    *(u32*)(Ch + (size_t)(row0+8)*Dm + col) = H1.u;
    *(u32*)(Cl + (size_t)row0*Dm + col)     = L0.u;
    *(u32*)(Cl + (size_t)(row0+8)*Dm + col) = L1.u;
}

template<int EPI>
__global__ __launch_bounds__(256, 2) void gemm_bf(
    const bf16* __restrict__ Ah, const bf16* __restrict__ Al,
    const bf16* __restrict__ Bh, const bf16* __restrict__ Bl,
    float* __restrict__ C, f16* __restrict__ Ch, f16* __restrict__ Cl)
{
    extern __shared__ char sm[];
    const u32 sb = s2u(sm);
    const int t = threadIdx.x;
    const int w = t >> 5, lane = t & 31;
    const int wm = w >> 2, wn = w & 3;
    const int bn = blockIdx.x, bm = blockIdx.y;

    const size_t arow = (size_t)bm * 128 * Dm;
    const size_t brow = (size_t)bn * 128 * Dm;

    float acc[4][4][4];
    #pragma unroll
    for (int i = 0; i < 4; i++)
        #pragma unroll
        for (int j = 0; j < 4; j++)
            #pragma unroll
            for (int q = 0; q < 4; q++) acc[i][j][q] = 0.f;

    load_tiles_bf(sb, 0, t, Ah, Al, Bh, Bl, arow, brow, 0);
    CPCOMMIT();

    const int lq = lane >> 2;
    const int lr = lane & 3;

    for (int c = 0; c < 64; c++) {
        const int buf = c & 1;
        CPWAIT(0);
        __syncthreads();
        if (c + 1 < 64) {
            load_tiles_bf(sb, buf ^ 1, t, Ah, Al, Bh, Bl, arow, brow, (c+1)*32);
            CPCOMMIT();
        }
        gemm_chunk_bf((const bf16*)(sm + OFF(0,buf)), (const bf16*)(sm + OFF(1,buf)),
                      (const bf16*)(sm + OFF(2,buf)), (const bf16*)(sm + OFF(3,buf)),
                      wm, wn, lq, lr, acc);
    }

    #pragma unroll
    for (int mt = 0; mt < 4; mt++) {
        #pragma unroll
        for (int nt = 0; nt < 4; nt++) {
            int row0 = bm*128 + wm*64 + mt*16 + lq;
            int col  = bn*128 + wn*32 + nt*8 + lr*2;
            float v0 = acc[mt][nt][0], v1 = acc[mt][nt][1];
            float v2 = acc[mt][nt][2], v3 = acc[mt][nt][3];
            if (EPI == EPI_HLF) {
                epi_store_hlf(Ch, Cl, row0, col, v0, v1, v2, v3);
            } else {
                *(float2*)(C + (size_t)row0*Dm + col)     = make_float2(v0, v1);
                *(float2*)(C + (size_t)(row0+8)*Dm + col) = make_float2(v2, v3);
            }
        }
    }
}

// ================= fp16 2-term batched GEMM — k, v, r, u ======================
// A single fp16 (one tile), B fp16 hi/lo (two tiles). CTA 128x128, BK=32.
#define FA_OFF(buf)  ((buf)*30720u)
#define FBH_OFF(buf) ((buf)*30720u + 10240u)
#define FBL_OFF(buf) ((buf)*30720u + 20480u)
#define SMEM_F16 61440

struct QSet {
    const f16* Bh; const f16* Bl; const float* bias;
    float* C; int epi;
};

__device__ __forceinline__ void load_tiles_f16(
    u32 sb, int buf, int t,
    const f16* A, const f16* Bh, const f16* Bl,
    size_t arow, size_t brow, int k0)
{
    #pragma unroll
    for (int p = 0; p < 2; p++) {
        int i = t + p*256;
        int r = i >> 2, c16 = i & 3;
        u32 dst = (u32)(r*80 + c16*16);
        size_t go = (size_t)r*Dm + k0 + c16*8;
        CPA(sb + FA_OFF(buf)  + dst, (const char*)(A  + arow + go));
        CPA(sb + FBH_OFF(buf) + dst, (const char*)(Bh + brow + go));
        CPA(sb + FBL_OFF(buf) + dst, (const char*)(Bl + brow + go));
    }
}

__device__ __forceinline__ void gemm_chunk_f16(
    const f16* sA, const f16* sBh, const f16* sBl,
    int wm, int wn, int lq, int lr, float (&acc)[4][4][4])
{
    #pragma unroll
    for (int ks = 0; ks < 2; ks++) {
        const int kofs = ks*16 + lr*2;
        u32 bh[4][2], bl[4][2];
        #pragma unroll
        for (int nt = 0; nt < 4; nt++) {
            int n0 = wn*32 + nt*8 + lq;
            bh[nt][0] = *(const u32*)(sBh + n0*40 + kofs);
            bh[nt][1] = *(const u32*)(sBh + n0*40 + kofs + 8);
            bl[nt][0] = *(const u32*)(sBl + n0*40 + kofs);
            bl[nt][1] = *(const u32*)(sBl + n0*40 + kofs + 8);
        }
        #pragma unroll
        for (int mt = 0; mt < 4; mt++) {
            int r0 = wm*64 + mt*16 + lq;
            u32 av[4];
            av[0] = *(const u32*)(sA + r0*40 + kofs);
            av[1] = *(const u32*)(sA + (r0+8)*40 + kofs);
            av[2] = *(const u32*)(sA + r0*40 + kofs + 8);
            av[3] = *(const u32*)(sA + (r0+8)*40 + kofs + 8);
            #pragma unroll
            for (int nt = 0; nt < 4; nt++) {
                mma_f16(acc[mt][nt], av, bh[nt]);
                mma_f16(acc[mt][nt], av, bl[nt]);
            }
        }
    }
}

__global__ __launch_bounds__(256, 2) void gemm_batch_f16(
    const f16* __restrict__ A,
    QSet g0, QSet g1, QSet g2, QSet g3)
{
    extern __shared__ char sm[];
    const u32 sb = s2u(sm);
    const int t = threadIdx.x;
    const int w = t >> 5, lane = t & 31;
    const int wm = w >> 2, wn = w & 3;
    const int bn = blockIdx.x, bm = blockIdx.y, z = blockIdx.z;

    const f16* Bh = (z==0) ? g0.Bh : (z==1) ? g1.Bh : (z==2) ? g2.Bh : g3.Bh;
    const f16* Bl = (z==0) ? g0.Bl : (z==1) ? g1.Bl : (z==2) ? g2.Bl : g3.Bl;

    const size_t arow = (size_t)bm * 128 * Dm;
    const size_t brow = (size_t)bn * 128 * Dm;

    float acc[4][4][4];
    #pragma unroll
    for (int i = 0; i < 4; i++)
        #pragma unroll
        for (int j = 0; j < 4; j++)
            #pragma unroll
            for (int q = 0; q < 4; q++) acc[i][j][q] = 0.f;

    load_tiles_f16(sb, 0, t, A, Bh, Bl, arow, brow, 0);
    CPCOMMIT();

    const int lq = lane >> 2;
    const int lr = lane & 3;

    for (int c = 0; c < 64; c++) {
        const int buf = c & 1;
        CPWAIT(0);
        __syncthreads();
        if (c + 1 < 64) {
            load_tiles_f16(sb, buf ^ 1, t, A, Bh, Bl, arow, brow, (c+1)*32);
            CPCOMMIT();
        }
        gemm_chunk_f16((const f16*)(sm + FA_OFF(buf)), (const f16*)(sm + FBH_OFF(buf)),
                       (const f16*)(sm + FBL_OFF(buf)), wm, wn, lq, lr, acc);
    }

    QSet gs = (z==0) ? g0 : (z==1) ? g1 : (z==2) ? g2 : g3;
    #pragma unroll
    for (int mt = 0; mt < 4; mt++) {
        #pragma unroll
        for (int nt = 0; nt < 4; nt++) {
            int row0 = bm*128 + wm*64 + mt*16 + lq;
            int col  = bn*128 + wn*32 + nt*8 + lr*2;
            float v0 = acc[mt][nt][0], v1 = acc[mt][nt][1];
            float v2 = acc[mt][nt][2], v3 = acc[mt][nt][3];
            if (gs.epi == EPI_SIG) {
                v0 = 1.0f/(1.0f+__expf(-v0)); v1 = 1.0f/(1.0f+__expf(-v1));
                v2 = 1.0f/(1.0f+__expf(-v2)); v3 = 1.0f/(1.0f+__expf(-v3));
            }
            if (gs.epi == EPI_USIG) {
                float bb0 = __ldg(gs.bias + col), bb1 = __ldg(gs.bias + col + 1);
                v0 = 1.0f/(1.0f+__expf(v0+bb0)); v1 = 1.0f/(1.0f+__expf(v1+bb1));
                v2 = 1.0f/(1.0f+__expf(v2+bb0)); v3 = 1.0f/(1.0f+__expf(v3+bb1));
            }
            *(float2*)(gs.C + (size_t)row0*Dm + col)     = make_float2(v0, v1);
            *(float2*)(gs.C + (size_t)(row0+8)*Dm + col) = make_float2(v2, v3);
        }
    }
}

// ---------------- selective-WKV recurrent scan (R16: packed f32x2) ------------
#define CH 8
__global__ __launch_bounds__(256) void scan_kernel(
    const float* __restrict__ kA, const float* __restrict__ vA,
    const float* __restrict__ uA, const float* __restrict__ rA,
    const float* __restrict__ state0, bf16* __restrict__ oh, bf16* __restrict__ ol,
    float* __restrict__ stateF)
{
    const int bh = blockIdx.x;
    const int b  = bh >> 5;
    const int h  = bh & 31;
    const size_t base = (size_t)b * Tt * Dm + (size_t)h * HSm;

    const int t  = threadIdx.x;
    const int ti = t >> 4;
    const int tj = t & 15;

    __shared__ float stg[2][4][CH][64];
    __shared__ float pS[CH][16][64];

    u64 S2[4][2];
    const float* st0 = state0 + (size_t)bh * 4096;
    #pragma unroll
    for (int ii = 0; ii < 4; ii++) {
        F4U2 sv; sv.f = *(const float4*)(st0 + (ti*4+ii)*64 + tj*4);
        S2[ii][0] = sv.u[0]; S2[ii][1] = sv.u[1];
    }

    const float* bases[4] = { kA + base, vA + base, uA + base, rA + base };

    const int i0 = t, i1 = t + 256;
    const int a0 = i0 >> 7, s0 = (i0 >> 4) & 7, q0 = i0 & 15;
    const int a1 = i1 >> 7, s1 = (i1 >> 4) & 7, q1 = i1 & 15;

    {
        u32 d0 = s2u(&stg[0][a0][s0][q0*4]);
        u32 d1 = s2u(&stg[0][a1][s1][q1*4]);
        CPA(d0, (const char*)(bases[a0] + (size_t)s0*Dm + q0*4));
        CPA(d1, (const char*)(bases[a1] + (size_t)s1*Dm + q1*4));
        CPCOMMIT();
    }

    for (int c = 0; c < Tt/CH; c++) {
        const int buf = c & 1;
        CPWAIT(0);
        __syncthreads();
        if (c + 1 < Tt/CH) {
            const size_t nco = (size_t)(c+1) * CH * Dm;
            u32 d0 = s2u(&stg[buf^1][a0][s0][q0*4]);
            u32 d1 = s2u(&stg[buf^1][a1][s1][q1*4]);
            CPA(d0, (const char*)(bases[a0] + nco + (size_t)s0*Dm + q0*4));
            CPA(d1, (const char*)(bases[a1] + nco + (size_t)s1*Dm + q1*4));
            CPCOMMIT();
        }

        #pragma unroll
        for (int s = 0; s < CH; s++) {
            float4 k4 = *(const float4*)(&stg[buf][0][s][ti*4]);
            float4 u4 = *(const float4*)(&stg[buf][2][s][ti*4]);
            float4 r4 = *(const float4*)(&stg[buf][3][s][ti*4]);
            F4U2 vv;  vv.f = *(const float4*)(&stg[buf][1][s][tj*4]);
            float ka[4] = {k4.x,k4.y,k4.z,k4.w};
            float ua[4] = {u4.x,u4.y,u4.z,u4.w};
            float ra[4] = {r4.x,r4.y,r4.z,r4.w};
            u64 p0 = 0ull, p1 = 0ull;
            #pragma unroll
            for (int ii = 0; ii < 4; ii++) {
                u64 kp, up, rp, t0, t1;
                PK2(kp, ka[ii]); PK2(up, ua[ii]); PK2(rp, ra[ii]);
                MUL2(t0, kp, vv.u[0]);
                MUL2(t1, kp, vv.u[1]);
                FMA2(S2[ii][0], up, S2[ii][0], t0);
                FMA2(S2[ii][1], up, S2[ii][1], t1);
                FMA2(p0, rp, S2[ii][0], p0);
                FMA2(p1, rp, S2[ii][1], p1);
            }
            F4U2 ps; ps.u[0] = p0; ps.u[1] = p1;
            *(float4*)(&pS[s][ti][tj*4]) = ps.f;
        }
        __syncthreads();

        const size_t coff = (size_t)c * CH * Dm;
        #pragma unroll
        for (int q = 0; q < 2; q++) {
            int o = t + q*256;
            int s = o >> 6;
            int j = o & 63;
            float sum = 0.f;
            #pragma unroll
            for (int ii = 0; ii < 16; ii++) sum += pS[s][ii][j];
            size_t idx = base + coff + (size_t)s*Dm + j;
            bf16 hv = __float2bfloat16(sum);
            oh[idx] = hv;
            ol[idx] = __float2bfloat16(sum - __bfloat162float(hv));
        }
        __syncthreads();
    }

    float* sf = stateF + (size_t)bh * 4096;
    #pragma unroll
    for (int ii = 0; ii < 4; ii++) {
        F4U2 sv; sv.u[0] = S2[ii][0]; sv.u[1] = S2[ii][1];
        *(float4*)(sf + (ti*4+ii)*64 + tj*4) = sv.f;
    }
}

// ---------------- launch ------------------------------------------------------
extern "C" void kernel_launch(void* const* d_in, const int* in_sizes, int n_in,
                              void* d_out, int out_size)
{
    const float* x     = (const float*)d_in[0];
    const float* state = (const float*)d_in[1];
    const float* ln_g  = (const float*)d_in[2];
    const float* ln_b  = (const float*)d_in[3];
    const float* Wx    = (const float*)d_in[4];
    const float* Ww    = (const float*)d_in[5];
    const float* bw    = (const float*)d_in[6];
    const float* Wk    = (const float*)d_in[7];
    const float* Wv    = (const float*)d_in[8];
    const float* Wr    = (const float*)d_in[9];
    const float* Wo    = (const float*)d_in[10];

    float* y_out  = (float*)d_out;
    float* sf_out = (float*)d_out + YSZ;

    float *kk, *vv, *uu, *rr;
    f16 *xn, *fhbase, *flbase;
    bf16 *oh, *ol, *whbase, *wlbase;
    cudaGetSymbolAddress((void**)&kk,  g_k);
    cudaGetSymbolAddress((void**)&vv,  g_v);
    cudaGetSymbolAddress((void**)&uu,  g_u);
    cudaGetSymbolAddress((void**)&rr,  g_r);
    cudaGetSymbolAddress((void**)&xn,  g_xn);
    cudaGetSymbolAddress((void**)&oh,  g_oh);
    cudaGetSymbolAddress((void**)&ol,  g_ol);
    cudaGetSymbolAddress((void**)&whbase, g_Wh);
    cudaGetSymbolAddress((void**)&wlbase, g_Wl);
    cudaGetSymbolAddress((void**)&fhbase, g_Fh);
    cudaGetSymbolAddress((void**)&flbase, g_Fl);
    bf16 *wh[3], *wl[3];
    f16  *fh[4], *fl[4];
    for (int i = 0; i < 3; i++) { wh[i] = whbase + (size_t)i*WSZ; wl[i] = wlbase + (size_t)i*WSZ; }
    for (int i = 0; i < 4; i++) { fh[i] = fhbase + (size_t)i*WSZ; fl[i] = flbase + (size_t)i*WSZ; }

    cudaFuncSetAttribute(gemm_batch_f16,     cudaFuncAttributeMaxDynamicSharedMemorySize, SMEM_F16);
    cudaFuncSetAttribute(gemm_bf<EPI_HLF>,   cudaFuncAttributeMaxDynamicSharedMemorySize, SMEM_BF);
    cudaFuncSetAttribute(gemm_bf<EPI_NONE>,  cudaFuncAttributeMaxDynamicSharedMemorySize, SMEM_BF);

    // launch 0: weight prep
    {
        dim3 cg(4096, 6);
        conv_all<<<cg, 256>>>(Wx, Ww, Wo, Wk, Wv, Wr, whbase, wlbase, fhbase, flbase);
    }

    // launch 1: LayerNorm -> fp16 xn
    ln_kernel<<<MROWS, 256>>>(x, ln_g, ln_b, xn);

    // launch 2: Wf = Ww @ Wx (bf16x3, output fp16 hi/lo into F3)
    {
        dim3 gw(Dm/128, Dm/128);
        gemm_bf<EPI_HLF><<<gw, 256, SMEM_BF>>>(wh[1], wl[1], wh[0], wl[0],
                                               nullptr, fh[3], fl[3]);
    }

    // launch 3: batched fp16 2-term GEMMs over xn: Wf (USIG->u), Wk, Wv, Wr (SIG)
    {
        QSet s0 = { fh[3], fl[3], bw, uu, EPI_USIG };
        QSet s1 = { fh[0], fl[0], nullptr, kk, EPI_NONE };
        QSet s2 = { fh[1], fl[1], nullptr, vv, EPI_NONE };
        QSet s3 = { fh[2], fl[2], nullptr, rr, EPI_SIG };
        dim3 gg(Dm/128, MROWS/128, 4);
        gemm_batch_f16<<<gg, 256, SMEM_F16>>>(xn, s0, s1, s2, s3);
    }

    // launch 4: scan
    scan_kernel<<<Bb*Hh, 256>>>(kk, vv, uu, rr, state, oh, ol, sf_out);

    // launch 5: y = outs @ Wo^T (bf16x3)
    {
        dim3 g1(Dm/128, MROWS/128);
        gemm_bf<EPI_NONE><<<g1, 256, SMEM_BF>>>(oh, ol, wh[2], wl[2],
                                                y_out, nullptr, nullptr);
    }
}